// round 8
// baseline (speedup 1.0000x reference)
#include <cuda_runtime.h>
#include <cuda_bf16.h>
#include <math.h>
#include <stdint.h>

// ---------------- model constants ----------------
#define BS    64
#define T_    96
#define C_    16
#define IN_   16
#define H_    256
#define NH_   8
#define DH_   32
#define NCLS  4
#define L_    100          // T + NCLS
#define LAYERS 4
#define BP    (BS * C_)    // 1024 sequences
#define ROWS  (BP * L_)    // 102400 token rows
#define EPS_  1e-5f

// ================= low-level helpers =================
__device__ __forceinline__ uint32_t smem_u32(const void* p) {
    uint32_t a;
    asm("{ .reg .u64 t; cvta.to.shared.u64 t, %1; cvt.u32.u64 %0, t; }"
        : "=r"(a) : "l"(p));
    return a;
}
__device__ __forceinline__ void cp16(uint32_t dst, const void* src) {
    asm volatile("cp.async.cg.shared.global [%0], [%1], 16;" :: "r"(dst), "l"(src) : "memory");
}
__device__ __forceinline__ void ldsm4(uint32_t* r, uint32_t addr) {
    asm volatile("ldmatrix.sync.aligned.m8n8.x4.shared.b16 {%0,%1,%2,%3}, [%4];"
        : "=r"(r[0]), "=r"(r[1]), "=r"(r[2]), "=r"(r[3]) : "r"(addr));
}
__device__ __forceinline__ void ldsm2(uint32_t* r, uint32_t addr) {
    asm volatile("ldmatrix.sync.aligned.m8n8.x2.shared.b16 {%0,%1}, [%2];"
        : "=r"(r[0]), "=r"(r[1]) : "r"(addr));
}
__device__ __forceinline__ void mma16816(float* d, const uint32_t* a, const uint32_t* b) {
    asm volatile("mma.sync.aligned.m16n8k16.row.col.f32.bf16.bf16.f32 "
        "{%0,%1,%2,%3}, {%4,%5,%6,%7}, {%8,%9}, {%0,%1,%2,%3};"
        : "+f"(d[0]), "+f"(d[1]), "+f"(d[2]), "+f"(d[3])
        : "r"(a[0]), "r"(a[1]), "r"(a[2]), "r"(a[3]), "r"(b[0]), "r"(b[1]));
}

// ---------------- bf16 split helper ----------------
__device__ __forceinline__ void split_bf16(float v, __nv_bfloat16& hi, __nv_bfloat16& lo) {
    hi = __float2bfloat16(v);
    lo = __float2bfloat16(v - __bfloat162float(hi));
}

// ---------------- scratch (device globals) -------------
__device__ __align__(256) float         g_h  [(size_t)ROWS * H_];
__device__ __align__(256) __nv_bfloat16 g_hh [(size_t)ROWS * H_];
__device__ __align__(256) __nv_bfloat16 g_hl [(size_t)ROWS * H_];
__device__ __align__(256) float         g_qkv[(size_t)ROWS * 3 * H_];
__device__ __align__(256) __nv_bfloat16 g_ah [(size_t)ROWS * H_];
__device__ __align__(256) __nv_bfloat16 g_al [(size_t)ROWS * H_];
__device__ __align__(256) float         g_t1 [(size_t)ROWS * H_];
__device__ __align__(256) __nv_bfloat16 g_f1h[(size_t)ROWS * 4 * H_];
__device__ __align__(256) __nv_bfloat16 g_f1l[(size_t)ROWS * 4 * H_];
// weights (bf16 pairs)
__device__ __align__(256) __nv_bfloat16 g_wqkvh[LAYERS * 3 * H_ * H_], g_wqkvl[LAYERS * 3 * H_ * H_];
__device__ __align__(256) __nv_bfloat16 g_woh  [LAYERS * H_ * H_],     g_wol  [LAYERS * H_ * H_];
__device__ __align__(256) __nv_bfloat16 g_w1h  [LAYERS * 4 * H_ * H_], g_w1l  [LAYERS * 4 * H_ * H_];
__device__ __align__(256) __nv_bfloat16 g_w2h  [LAYERS * 4 * H_ * H_], g_w2l  [LAYERS * 4 * H_ * H_];
__device__ __align__(256) __nv_bfloat16 g_wmh  [(LAYERS-1) * H_ * 3 * H_], g_wml[(LAYERS-1) * H_ * 3 * H_];
// graph / mixprop
__device__ float g_m1 [C_ * H_];
__device__ float g_m2 [C_ * H_];
__device__ float g_adj[C_ * C_];
__device__ __align__(256) float         g_ho [(size_t)BS * C_ * NCLS * 3 * H_];
__device__ __align__(256) __nv_bfloat16 g_hoh[(size_t)BS * C_ * NCLS * 3 * H_];
__device__ __align__(256) __nv_bfloat16 g_hol[(size_t)BS * C_ * NCLS * 3 * H_];
__device__ __align__(256) float g_mpo[(size_t)BS * C_ * NCLS * H_];
__device__ __align__(256) float g_z  [(size_t)BS * C_ * NCLS * H_];
__device__ float g_d1 [BS * H_];

// ================= HMMA GEMM (bf16x3, mma.sync, 3-stage pipeline) =========
// C[M,N] = A[M,K] @ B[N,K]^T + bias.  mode 0: fp32 out; mode 1: relu + bf16 pair.
// grid = (N/128, M/128), 256 threads. M,N %128 == 0, K %32 == 0, K/32 >= 2.
#define ASTR    40                        // bf16 row pitch (80B) — conflict-free
#define TILE_B  (128 * ASTR * 2)          // 10240 bytes per buffer
#define STAGE_B (4 * TILE_B)              // Ah, Al, Bh, Bl
#define NSTAGE  3
#define SMEM_GEMM_BYTES (NSTAGE * STAGE_B)  // 122880
#define OFF_AH  0
#define OFF_AL  TILE_B
#define OFF_BH  (2 * TILE_B)
#define OFF_BL  (3 * TILE_B)

__global__ __launch_bounds__(256) void gemm_bf3_kernel(
    const __nv_bfloat16* __restrict__ Ah, const __nv_bfloat16* __restrict__ Al,
    const __nv_bfloat16* __restrict__ Bh, const __nv_bfloat16* __restrict__ Bl,
    const float* __restrict__ bias,
    float* __restrict__ Cf, __nv_bfloat16* __restrict__ Ch, __nv_bfloat16* __restrict__ Cl,
    int M, int N, int K, int mode)
{
    extern __shared__ char smem[];
    uint32_t sb = smem_u32(smem);
    int tid = threadIdx.x;
    int lane = tid & 31;
    int w = tid >> 5;
    int wm = w >> 2;            // 0..1
    int wn = w & 3;             // 0..3
    int m0 = blockIdx.y * 128, n0 = blockIdx.x * 128;

    float acc[4][4][4];
    #pragma unroll
    for (int i = 0; i < 4; i++)
        #pragma unroll
        for (int j = 0; j < 4; j++)
            #pragma unroll
            for (int k = 0; k < 4; k++) acc[i][j][k] = 0.f;

    int nch = K >> 5;

    // ---- stage loader: 128 rows x 32 bf16 per buffer; 2 x 16B per thread ----
    #define ISSUE_STAGE(cidx, bidx) do {                                         \
        int _kc = (cidx) << 5;                                                   \
        uint32_t _base = sb + (uint32_t)(bidx) * STAGE_B;                        \
        _Pragma("unroll")                                                        \
        for (int _i = 0; _i < 2; _i++) {                                         \
            int _id = tid + _i * 256;                                            \
            int _r = _id >> 2;                                                   \
            int _cc = (_id & 3) << 3;                                            \
            uint32_t _do = (uint32_t)(_r * (ASTR * 2) + _cc * 2);                \
            size_t _ga = (size_t)(m0 + _r) * K + _kc + _cc;                      \
            size_t _gb = (size_t)(n0 + _r) * K + _kc + _cc;                      \
            cp16(_base + OFF_AH + _do, Ah + _ga);                                \
            cp16(_base + OFF_AL + _do, Al + _ga);                                \
            cp16(_base + OFF_BH + _do, Bh + _gb);                                \
            cp16(_base + OFF_BL + _do, Bl + _gb);                                \
        }                                                                        \
        asm volatile("cp.async.commit_group;" ::: "memory");                     \
    } while (0)

    ISSUE_STAGE(0, 0);
    ISSUE_STAGE(1, 1);

    for (int c = 0; c < nch; c++) {
        if (c < nch - 1) asm volatile("cp.async.wait_group 1;" ::: "memory");
        else             asm volatile("cp.async.wait_group 0;" ::: "memory");
        __syncthreads();
        if (c + 2 < nch) ISSUE_STAGE(c + 2, (c + 2) % NSTAGE);

        uint32_t base = sb + (uint32_t)(c % NSTAGE) * STAGE_B;
        #pragma unroll
        for (int ks = 0; ks < 2; ks++) {
            uint32_t ah[4][4], al[4][4], bh[4][2], bl[4][2];
            int arow = wm * 64 + (lane & 15);
            int akc  = ks * 16 + (lane >> 4) * 8;
            #pragma unroll
            for (int mf = 0; mf < 4; mf++) {
                uint32_t off = (uint32_t)(((arow + mf * 16) * ASTR + akc) * 2);
                ldsm4(ah[mf], base + OFF_AH + off);
                ldsm4(al[mf], base + OFF_AL + off);
            }
            int brow = wn * 32 + (lane & 7);
            int bkc  = ks * 16 + (((lane & 15) >> 3)) * 8;
            #pragma unroll
            for (int nf = 0; nf < 4; nf++) {
                uint32_t off = (uint32_t)(((brow + nf * 8) * ASTR + bkc) * 2);
                ldsm2(bh[nf], base + OFF_BH + off);
                ldsm2(bl[nf], base + OFF_BL + off);
            }
            // pass-reordered MMAs: same per-acc accumulation order (hh, hl, lh)
            // but RAW spacing of 16 instructions instead of 1
            #pragma unroll
            for (int mf = 0; mf < 4; mf++)
                #pragma unroll
                for (int nf = 0; nf < 4; nf++)
                    mma16816(acc[mf][nf], ah[mf], bh[nf]);
            #pragma unroll
            for (int mf = 0; mf < 4; mf++)
                #pragma unroll
                for (int nf = 0; nf < 4; nf++)
                    mma16816(acc[mf][nf], ah[mf], bl[nf]);
            #pragma unroll
            for (int mf = 0; mf < 4; mf++)
                #pragma unroll
                for (int nf = 0; nf < 4; nf++)
                    mma16816(acc[mf][nf], al[mf], bh[nf]);
        }
    }

    // ---- epilogue ----
    int rbase = m0 + wm * 64 + (lane >> 2);
    int cbase = n0 + wn * 32 + (lane & 3) * 2;
    #pragma unroll
    for (int mf = 0; mf < 4; mf++) {
        #pragma unroll
        for (int nf = 0; nf < 4; nf++) {
            int r = rbase + mf * 16;
            int cc = cbase + nf * 8;
            float b0 = bias[cc], b1 = bias[cc + 1];
            if (mode == 0) {
                float2 v0 = { acc[mf][nf][0] + b0, acc[mf][nf][1] + b1 };
                float2 v1 = { acc[mf][nf][2] + b0, acc[mf][nf][3] + b1 };
                *(float2*)(Cf + (size_t)r * N + cc)       = v0;
                *(float2*)(Cf + (size_t)(r + 8) * N + cc) = v1;
            } else {
                float v0 = fmaxf(acc[mf][nf][0] + b0, 0.f);
                float v1 = fmaxf(acc[mf][nf][1] + b1, 0.f);
                float v2 = fmaxf(acc[mf][nf][2] + b0, 0.f);
                float v3 = fmaxf(acc[mf][nf][3] + b1, 0.f);
                __nv_bfloat16 h0, l0, h1, l1, h2, l2, h3, l3;
                split_bf16(v0, h0, l0); split_bf16(v1, h1, l1);
                split_bf16(v2, h2, l2); split_bf16(v3, h3, l3);
                __nv_bfloat162 hh0; hh0.x = h0; hh0.y = h1;
                __nv_bfloat162 ll0; ll0.x = l0; ll0.y = l1;
                __nv_bfloat162 hh1; hh1.x = h2; hh1.y = h3;
                __nv_bfloat162 ll1; ll1.x = l2; ll1.y = l3;
                *(__nv_bfloat162*)(Ch + (size_t)r * N + cc)       = hh0;
                *(__nv_bfloat162*)(Cl + (size_t)r * N + cc)       = ll0;
                *(__nv_bfloat162*)(Ch + (size_t)(r + 8) * N + cc) = hh1;
                *(__nv_bfloat162*)(Cl + (size_t)(r + 8) * N + cc) = ll1;
            }
        }
    }
}

// ================= misc kernels =================
__global__ __launch_bounds__(256) void conv_pair_kernel(
    const float* __restrict__ s, __nv_bfloat16* __restrict__ hi,
    __nv_bfloat16* __restrict__ lo, int n)
{
    int i = blockIdx.x * 256 + threadIdx.x;
    if (i < n) {
        __nv_bfloat16 h, l;
        split_bf16(s[i], h, l);
        hi[i] = h; lo[i] = l;
    }
}

__global__ __launch_bounds__(256) void embed_kernel(
    const float* __restrict__ x, const float* __restrict__ Wfc,
    const float* __restrict__ bfc, const float* __restrict__ cls,
    const float* __restrict__ pos)
{
    int row = blockIdx.x;
    int l  = row % L_;
    int bc = row / L_;
    int c  = bc % C_;
    int b  = bc / C_;
    int t  = threadIdx.x;

    __shared__ float xs[IN_];
    float val;
    if (l < T_) {
        if (t < IN_) xs[t] = x[(((size_t)b * T_ + l) * C_ + c) * IN_ + t];
        __syncthreads();
        float s = bfc[t];
        #pragma unroll
        for (int i = 0; i < IN_; i++) s += xs[i] * Wfc[t * IN_ + i];
        val = s;
    } else {
        val = cls[((l - T_) * C_ + c) * H_ + t];
    }
    val += pos[((size_t)l * C_ + c) * H_ + t];
    size_t o = (size_t)row * H_ + t;
    g_h[o] = val;
    __nv_bfloat16 h, lo_;
    split_bf16(val, h, lo_);
    g_hh[o] = h; g_hl[o] = lo_;
}

__global__ __launch_bounds__(256) void graph_kernel(
    const float* __restrict__ emb1, const float* __restrict__ emb2,
    const float* __restrict__ Wl1, const float* __restrict__ bl1,
    const float* __restrict__ Wl2, const float* __restrict__ bl2)
{
    int t = threadIdx.x;
    for (int i = 0; i < C_; i++) {
        float s1 = bl1[t], s2 = bl2[t];
        for (int k = 0; k < H_; k++) {
            s1 += emb1[i * H_ + k] * Wl1[t * H_ + k];
            s2 += emb2[i * H_ + k] * Wl2[t * H_ + k];
        }
        g_m1[i * H_ + t] = tanhf(s1);
        g_m2[i * H_ + t] = tanhf(s2);
    }
    __syncthreads();

    __shared__ float adj[C_][C_];
    __shared__ float rsum[C_];
    int v = t >> 4, w = t & 15;
    float s = 0.f;
    for (int j = 0; j < H_; j++)
        s += g_m1[v * H_ + j] * g_m2[w * H_ + j]
           - g_m2[v * H_ + j] * g_m1[w * H_ + j];
    float gv = fmaxf(tanhf(s), 0.f);
    if (v == w) gv += 1.0f;
    adj[v][w] = gv;
    __syncthreads();
    if (t < C_) {
        float r = 0.f;
        for (int k = 0; k < C_; k++) r += adj[t][k];
        rsum[t] = r;
    }
    __syncthreads();
    g_adj[t] = adj[v][w] / rsum[v];
}

// ================= attention (3-phase, SMEM scores) =================
// block per (seq, head), 256 threads.
#define QP 36          // Q/K/V row pitch (floats) — float4-aligned, conflict-free
#define SP 101         // score row pitch — conflict-free column access
#define ATT_SMEM ((3 * L_ * QP + L_ * SP + L_) * 4)   // 84000 bytes

__global__ __launch_bounds__(256) void attn_kernel(const float* __restrict__ qkv)
{
    extern __shared__ float asmem[];
    float* Qs  = asmem;                  // [L_][QP]
    float* Ks  = Qs + L_ * QP;
    float* Vs  = Ks + L_ * QP;
    float* Ss  = Vs + L_ * QP;           // [L_][SP]
    float* inv = Ss + L_ * SP;           // [L_]

    int bh = blockIdx.x;
    int b = bh >> 3, h = bh & 7;
    int tid = threadIdx.x;
    int lane = tid & 31, w = tid >> 5;

    const float* base = qkv + (size_t)b * L_ * (3 * H_) + h * DH_;
    for (int idx = tid; idx < L_ * DH_; idx += 256) {
        int l = idx >> 5, d = idx & 31;
        const float* r = base + (size_t)l * (3 * H_) + d;
        Qs[l * QP + d] = r[0];
        Ks[l * QP + d] = r[H_];
        Vs[l * QP + d] = r[2 * H_];
    }
    __syncthreads();

    // ---- phase 1: scores. warp w: i-half (w>>2), j-block jb = w&3 ----
    {
        int jb = w & 3;
        int j = jb * 32 + lane;
        float kr[32];
        if (j < L_) {
            #pragma unroll
            for (int dc = 0; dc < 8; dc++) {
                float4 kv = *(const float4*)(Ks + j * QP + dc * 4);
                kr[dc * 4 + 0] = kv.x; kr[dc * 4 + 1] = kv.y;
                kr[dc * 4 + 2] = kv.z; kr[dc * 4 + 3] = kv.w;
            }
        }
        int i0 = (w >> 2) * 50;
        for (int i = i0; i < i0 + 50; i++) {
            if (i < T_ && jb * 32 > i) continue;   // whole j-block masked
            float a0 = 0.f, a1 = 0.f, a2 = 0.f, a3 = 0.f;
            #pragma unroll
            for (int dc = 0; dc < 8; dc++) {
                float4 qv = *(const float4*)(Qs + i * QP + dc * 4);
                a0 += qv.x * kr[dc * 4 + 0];
                a1 += qv.y * kr[dc * 4 + 1];
                a2 += qv.z * kr[dc * 4 + 2];
                a3 += qv.w * kr[dc * 4 + 3];
            }
            if (j < L_)
                Ss[i * SP + j] = (a0 + a1 + a2 + a3) * 0.17677669529663687f;
        }
    }
    __syncthreads();

    // ---- phase 2: softmax per row (exp stored unnormalized; 1/sum kept) ----
    if (tid < L_) {
        int i = tid;
        int jmax = (i >= T_) ? L_ : i + 1;
        float m = -1e30f;
        for (int j = 0; j < jmax; j++) m = fmaxf(m, Ss[i * SP + j]);
        float sum = 0.f;
        for (int j = 0; j < jmax; j++) {
            float p = __expf(Ss[i * SP + j] - m);
            Ss[i * SP + j] = p;
            sum += p;
        }
        for (int j = jmax; j < L_; j++) Ss[i * SP + j] = 0.f;
        inv[i] = 1.f / sum;
    }
    __syncthreads();

    // ---- phase 3: O = P V. warp w: i-block ib = w&3, d-chunk (w>>2)*16 ----
    {
        int ib = w & 3;
        int i = ib * 32 + lane;
        int dc0 = (w >> 2) * 16;
        float acc[16];
        #pragma unroll
        for (int t = 0; t < 16; t++) acc[t] = 0.f;
        int jmaxw = (ib < 3) ? (ib * 32 + 32) : L_;
        for (int j = 0; j < jmaxw; j++) {
            float p = (i < L_) ? Ss[i * SP + j] : 0.f;
            #pragma unroll
            for (int q4 = 0; q4 < 4; q4++) {
                float4 vv = *(const float4*)(Vs + j * QP + dc0 + q4 * 4);
                acc[q4 * 4 + 0] += p * vv.x;
                acc[q4 * 4 + 1] += p * vv.y;
                acc[q4 * 4 + 2] += p * vv.z;
                acc[q4 * 4 + 3] += p * vv.w;
            }
        }
        if (i < L_) {
            float sc = inv[i];
            size_t o = ((size_t)b * L_ + i) * H_ + h * DH_ + dc0;
            #pragma unroll
            for (int t = 0; t < 16; t += 2) {
                float v0 = acc[t] * sc, v1 = acc[t + 1] * sc;
                __nv_bfloat16 h0, l0, h1, l1;
                split_bf16(v0, h0, l0);
                split_bf16(v1, h1, l1);
                __nv_bfloat162 hh; hh.x = h0; hh.y = h1;
                __nv_bfloat162 ll; ll.x = l0; ll.y = l1;
                *(__nv_bfloat162*)(g_ah + o + t) = hh;
                *(__nv_bfloat162*)(g_al + o + t) = ll;
            }
        }
    }
}

// fused residual-add + LayerNorm; writes fp32 h and bf16 pair
__global__ __launch_bounds__(256) void add_ln_kernel(
    const float* __restrict__ xin,
    const float* __restrict__ g, const float* __restrict__ bt)
{
    int row = blockIdx.x, t = threadIdx.x;
    size_t base = (size_t)row * H_;
    float v = g_h[base + t] + xin[base + t];

    __shared__ float ws[8];
    float s = v;
    #pragma unroll
    for (int o = 16; o > 0; o >>= 1) s += __shfl_xor_sync(0xffffffffu, s, o);
    if ((t & 31) == 0) ws[t >> 5] = s;
    __syncthreads();
    float tot = 0.f;
    #pragma unroll
    for (int i = 0; i < 8; i++) tot += ws[i];
    float mean = tot * (1.0f / H_);
    float d = v - mean;
    __syncthreads();

    float q = d * d;
    #pragma unroll
    for (int o = 16; o > 0; o >>= 1) q += __shfl_xor_sync(0xffffffffu, q, o);
    if ((t & 31) == 0) ws[t >> 5] = q;
    __syncthreads();
    float qt = 0.f;
    #pragma unroll
    for (int i = 0; i < 8; i++) qt += ws[i];
    float var = qt * (1.0f / H_);

    float out = d * rsqrtf(var + EPS_) * g[t] + bt[t];
    g_h[base + t] = out;
    __nv_bfloat16 hh, ll;
    split_bf16(out, hh, ll);
    g_hh[base + t] = hh; g_hl[base + t] = ll;
}

// ---------------- mixprop helpers -----------------
__global__ __launch_bounds__(256) void mp_gather_kernel()
{
    int idx = blockIdx.x * 256 + threadIdx.x;
    int hd = idx & 255;
    int r  = idx >> 8;
    int l  = r & 3;
    int nw = r >> 2;
    g_ho[(size_t)r * (3 * H_) + hd] = g_h[((size_t)nw * L_ + T_ + l) * H_ + hd];
}

__global__ __launch_bounds__(256) void mp_prop_kernel(int depth)
{
    int idx = blockIdx.x * 256 + threadIdx.x;
    int hd = idx & 255;
    int r  = idx >> 8;
    int l  = r & 3;
    int v  = (r >> 2) & 15;
    int n  = r >> 6;
    float s = 0.f;
    #pragma unroll
    for (int w = 0; w < C_; w++)
        s += g_adj[v * C_ + w] *
             g_ho[(size_t)(((n * C_ + w) << 2) + l) * (3 * H_) + (depth - 1) * H_ + hd];
    g_ho[(size_t)r * (3 * H_) + depth * H_ + hd] = s;
}

__global__ __launch_bounds__(256) void mp_scatter_kernel()
{
    int idx = blockIdx.x * 256 + threadIdx.x;
    int o  = idx & 255;
    int r  = idx >> 8;
    int l  = r & 3;
    int nw = r >> 2;
    float v = g_mpo[(size_t)r * H_ + o];
    size_t dst = ((size_t)nw * L_ + T_ + l) * H_ + o;
    g_h[dst] = v;
    __nv_bfloat16 hh, ll;
    split_bf16(v, hh, ll);
    g_hh[dst] = hh; g_hl[dst] = ll;
}

// ---------------- head ----------------
__global__ __launch_bounds__(256) void tanh_gather_kernel()
{
    int idx = blockIdx.x * 256 + threadIdx.x;
    int hd = idx & 255;
    int r  = idx >> 8;
    int n  = r & 3;
    int c  = (r >> 2) & 15;
    int b  = r >> 6;
    g_z[idx] = tanhf(g_h[(((size_t)(b * C_ + c)) * L_ + T_ + n) * H_ + hd]);
}

// 64 blocks (per batch), 512 threads; z row cached in SMEM (64KB)
__global__ __launch_bounds__(512) void head_gemm_kernel(
    const float* __restrict__ Wd1, const float* __restrict__ bd1)
{
    extern __shared__ float zs[];
    int b = blockIdx.x;
    int tid = threadIdx.x;
    for (int i = tid; i < C_ * NCLS * H_; i += 512)
        zs[i] = g_z[(size_t)b * (C_ * NCLS * H_) + i];
    __syncthreads();
    int wid = tid >> 5, lane = tid & 31;
    for (int o = wid; o < H_; o += 16) {
        const float* w = Wd1 + (size_t)o * (C_ * NCLS * H_);
        float s = 0.f;
        for (int k = lane; k < C_ * NCLS * H_; k += 32)
            s += zs[k] * w[k];
        #pragma unroll
        for (int off = 16; off > 0; off >>= 1)
            s += __shfl_xor_sync(0xffffffffu, s, off);
        if (lane == 0) g_d1[b * H_ + o] = s + bd1[o];
    }
}

__global__ __launch_bounds__(256) void head_kernel(
    const float* __restrict__ Wd2, const float* __restrict__ bd2,
    float* __restrict__ out)
{
    int b = blockIdx.x, t = threadIdx.x;
    float x = g_d1[b * H_ + t];
    float gl = 0.5f * x * (1.0f + erff(x * 0.70710678118654752f));
    float v = gl * Wd2[t];
    #pragma unroll
    for (int o = 16; o > 0; o >>= 1) v += __shfl_xor_sync(0xffffffffu, v, o);
    __shared__ float ws[8];
    if ((t & 31) == 0) ws[t >> 5] = v;
    __syncthreads();
    if (t == 0) {
        float s = 0.f;
        #pragma unroll
        for (int i = 0; i < 8; i++) s += ws[i];
        out[b] = s + bd2[0];
    }
}

// ---------------- host ----------------
static float* dev_ptr(const void* symbol)
{
    void* p = nullptr;
    cudaGetSymbolAddress(&p, symbol);
    return (float*)p;
}
static __nv_bfloat16* dev_ptr_b(const void* symbol)
{
    void* p = nullptr;
    cudaGetSymbolAddress(&p, symbol);
    return (__nv_bfloat16*)p;
}

extern "C" void kernel_launch(void* const* d_in, const int* in_sizes, int n_in,
                              void* d_out, int out_size)
{
    const float* x        = (const float*)d_in[0];
    const float* Wfc      = (const float*)d_in[3];
    const float* bfc      = (const float*)d_in[4];
    const float* cls_tok  = (const float*)d_in[5];
    const float* pos_emb  = (const float*)d_in[6];
    const float* emb1     = (const float*)d_in[7];
    const float* emb2     = (const float*)d_in[8];
    const float* Wl1      = (const float*)d_in[9];
    const float* bl1      = (const float*)d_in[10];
    const float* Wl2      = (const float*)d_in[11];
    const float* bl2      = (const float*)d_in[12];
    const float* Wqkv     = (const float*)d_in[13];
    const float* bqkv     = (const float*)d_in[14];
    const float* Wo       = (const float*)d_in[15];
    const float* bo       = (const float*)d_in[16];
    const float* W1       = (const float*)d_in[17];
    const float* b1       = (const float*)d_in[18];
    const float* W2       = (const float*)d_in[19];
    const float* b2       = (const float*)d_in[20];
    const float* ln1g     = (const float*)d_in[21];
    const float* ln1b     = (const float*)d_in[22];
    const float* ln2g     = (const float*)d_in[23];
    const float* ln2b     = (const float*)d_in[24];
    const float* Wmlp     = (const float*)d_in[25];
    const float* bmlp     = (const float*)d_in[26];
    const float* Wd1      = (const float*)d_in[27];
    const float* bd1      = (const float*)d_in[28];
    const float* Wd2      = (const float*)d_in[29];
    const float* bd2      = (const float*)d_in[30];
    float* out = (float*)d_out;

    static bool inited = false;
    static float *p_h, *p_qkv, *p_t1, *p_mpo, *p_ho;
    static __nv_bfloat16 *p_hh, *p_hl, *p_ah, *p_al, *p_f1h, *p_f1l;
    static __nv_bfloat16 *p_wqkvh, *p_wqkvl, *p_woh, *p_wol, *p_w1h, *p_w1l,
                         *p_w2h, *p_w2l, *p_wmh, *p_wml, *p_hoh, *p_hol;
    if (!inited) {
        cudaFuncSetAttribute(gemm_bf3_kernel,
            cudaFuncAttributeMaxDynamicSharedMemorySize, SMEM_GEMM_BYTES);
        cudaFuncSetAttribute(attn_kernel,
            cudaFuncAttributeMaxDynamicSharedMemorySize, ATT_SMEM);
        cudaFuncSetAttribute(head_gemm_kernel,
            cudaFuncAttributeMaxDynamicSharedMemorySize, C_ * NCLS * H_ * 4);
        p_h = dev_ptr(g_h); p_qkv = dev_ptr(g_qkv); p_t1 = dev_ptr(g_t1);
        p_mpo = dev_ptr(g_mpo); p_ho = dev_ptr(g_ho);
        p_hh = dev_ptr_b(g_hh); p_hl = dev_ptr_b(g_hl);
        p_ah = dev_ptr_b(g_ah); p_al = dev_ptr_b(g_al);
        p_f1h = dev_ptr_b(g_f1h); p_f1l = dev_ptr_b(g_f1l);
        p_wqkvh = dev_ptr_b(g_wqkvh); p_wqkvl = dev_ptr_b(g_wqkvl);
        p_woh = dev_ptr_b(g_woh); p_wol = dev_ptr_b(g_wol);
        p_w1h = dev_ptr_b(g_w1h); p_w1l = dev_ptr_b(g_w1l);
        p_w2h = dev_ptr_b(g_w2h); p_w2l = dev_ptr_b(g_w2l);
        p_wmh = dev_ptr_b(g_wmh); p_wml = dev_ptr_b(g_wml);
        p_hoh = dev_ptr_b(g_hoh); p_hol = dev_ptr_b(g_hol);
        inited = true;
    }

    // weight conversion (fp32 -> bf16 hi/lo)
    conv_pair_kernel<<<(LAYERS * 3 * H_ * H_) / 256, 256>>>(Wqkv, p_wqkvh, p_wqkvl, LAYERS * 3 * H_ * H_);
    conv_pair_kernel<<<(LAYERS * H_ * H_) / 256, 256>>>(Wo, p_woh, p_wol, LAYERS * H_ * H_);
    conv_pair_kernel<<<(LAYERS * 4 * H_ * H_) / 256, 256>>>(W1, p_w1h, p_w1l, LAYERS * 4 * H_ * H_);
    conv_pair_kernel<<<(LAYERS * 4 * H_ * H_) / 256, 256>>>(W2, p_w2h, p_w2l, LAYERS * 4 * H_ * H_);
    conv_pair_kernel<<<((LAYERS - 1) * H_ * 3 * H_) / 256, 256>>>(Wmlp, p_wmh, p_wml, (LAYERS - 1) * H_ * 3 * H_);

    graph_kernel<<<1, 256>>>(emb1, emb2, Wl1, bl1, Wl2, bl2);
    embed_kernel<<<ROWS, 256>>>(x, Wfc, bfc, cls_tok, pos_emb);

    const int MP_THREADS = BS * C_ * NCLS * H_;   // 1,048,576
    const int HO_N = BS * C_ * NCLS * 3 * H_;     // 3,145,728

    for (int l = 0; l < LAYERS; l++) {
        if (l > 0) {
            mp_gather_kernel<<<MP_THREADS / 256, 256>>>();
            mp_prop_kernel<<<MP_THREADS / 256, 256>>>(1);
            mp_prop_kernel<<<MP_THREADS / 256, 256>>>(2);
            conv_pair_kernel<<<HO_N / 256, 256>>>(p_ho, p_hoh, p_hol, HO_N);
            gemm_bf3_kernel<<<dim3(2, 32), 256, SMEM_GEMM_BYTES>>>(
                p_hoh, p_hol,
                p_wmh + (size_t)(l - 1) * H_ * 3 * H_, p_wml + (size_t)(l - 1) * H_ * 3 * H_,
                bmlp + (size_t)(l - 1) * H_,
                p_mpo, nullptr, nullptr,
                BS * C_ * NCLS, H_, 3 * H_, 0);
            mp_scatter_kernel<<<MP_THREADS / 256, 256>>>();
        }

        // QKV projection
        gemm_bf3_kernel<<<dim3(6, ROWS / 128), 256, SMEM_GEMM_BYTES>>>(
            p_hh, p_hl,
            p_wqkvh + (size_t)l * 3 * H_ * H_, p_wqkvl + (size_t)l * 3 * H_ * H_,
            bqkv + (size_t)l * 3 * H_,
            p_qkv, nullptr, nullptr, ROWS, 3 * H_, H_, 0);

        attn_kernel<<<BP * NH_, 256, ATT_SMEM>>>(p_qkv);

        // output projection -> g_t1
        gemm_bf3_kernel<<<dim3(2, ROWS / 128), 256, SMEM_GEMM_BYTES>>>(
            p_ah, p_al,
            p_woh + (size_t)l * H_ * H_, p_wol + (size_t)l * H_ * H_,
            bo + (size_t)l * H_,
            p_t1, nullptr, nullptr, ROWS, H_, H_, 0);

        add_ln_kernel<<<ROWS, 256>>>(p_t1, ln1g + l * H_, ln1b + l * H_);

        // FFN
        gemm_bf3_kernel<<<dim3(8, ROWS / 128), 256, SMEM_GEMM_BYTES>>>(
            p_hh, p_hl,
            p_w1h + (size_t)l * 4 * H_ * H_, p_w1l + (size_t)l * 4 * H_ * H_,
            b1 + (size_t)l * 4 * H_,
            nullptr, p_f1h, p_f1l, ROWS, 4 * H_, H_, 1);

        gemm_bf3_kernel<<<dim3(2, ROWS / 128), 256, SMEM_GEMM_BYTES>>>(
            p_f1h, p_f1l,
            p_w2h + (size_t)l * 4 * H_ * H_, p_w2l + (size_t)l * 4 * H_ * H_,
            b2 + (size_t)l * H_,
            p_t1, nullptr, nullptr, ROWS, H_, 4 * H_, 0);

        add_ln_kernel<<<ROWS, 256>>>(p_t1, ln2g + l * H_, ln2b + l * H_);
    }

    tanh_gather_kernel<<<MP_THREADS / 256, 256>>>();
    head_gemm_kernel<<<BS, 512, C_ * NCLS * H_ * 4>>>(Wd1, bd1);
    head_kernel<<<BS, 256>>>(Wd2, bd2, out);
}

// round 9
// speedup vs baseline: 1.1466x; 1.1466x over previous
#include <cuda_runtime.h>
#include <cuda_bf16.h>
#include <math.h>
#include <stdint.h>

// ---------------- model constants ----------------
#define BS    64
#define T_    96
#define C_    16
#define IN_   16
#define H_    256
#define NH_   8
#define DH_   32
#define NCLS  4
#define L_    100          // T + NCLS
#define LAYERS 4
#define BP    (BS * C_)    // 1024 sequences
#define ROWS  (BP * L_)    // 102400 token rows
#define EPS_  1e-5f

// ================= low-level helpers =================
__device__ __forceinline__ uint32_t smem_u32(const void* p) {
    uint32_t a;
    asm("{ .reg .u64 t; cvta.to.shared.u64 t, %1; cvt.u32.u64 %0, t; }"
        : "=r"(a) : "l"(p));
    return a;
}
__device__ __forceinline__ void cp16(uint32_t dst, const void* src) {
    asm volatile("cp.async.cg.shared.global [%0], [%1], 16;" :: "r"(dst), "l"(src) : "memory");
}
__device__ __forceinline__ void ldsm4(uint32_t* r, uint32_t addr) {
    asm volatile("ldmatrix.sync.aligned.m8n8.x4.shared.b16 {%0,%1,%2,%3}, [%4];"
        : "=r"(r[0]), "=r"(r[1]), "=r"(r[2]), "=r"(r[3]) : "r"(addr));
}
__device__ __forceinline__ void ldsm2(uint32_t* r, uint32_t addr) {
    asm volatile("ldmatrix.sync.aligned.m8n8.x2.shared.b16 {%0,%1}, [%2];"
        : "=r"(r[0]), "=r"(r[1]) : "r"(addr));
}
__device__ __forceinline__ void mma16816(float* d, const uint32_t* a, const uint32_t* b) {
    asm volatile("mma.sync.aligned.m16n8k16.row.col.f32.bf16.bf16.f32 "
        "{%0,%1,%2,%3}, {%4,%5,%6,%7}, {%8,%9}, {%0,%1,%2,%3};"
        : "+f"(d[0]), "+f"(d[1]), "+f"(d[2]), "+f"(d[3])
        : "r"(a[0]), "r"(a[1]), "r"(a[2]), "r"(a[3]), "r"(b[0]), "r"(b[1]));
}

// ---------------- bf16 split helper ----------------
__device__ __forceinline__ void split_bf16(float v, __nv_bfloat16& hi, __nv_bfloat16& lo) {
    hi = __float2bfloat16(v);
    lo = __float2bfloat16(v - __bfloat162float(hi));
}

// ---------------- scratch (device globals) -------------
__device__ __align__(256) float         g_h  [(size_t)ROWS * H_];
__device__ __align__(256) __nv_bfloat16 g_hh [(size_t)ROWS * H_];
__device__ __align__(256) __nv_bfloat16 g_hl [(size_t)ROWS * H_];
__device__ __align__(256) float         g_qkv[(size_t)ROWS * 3 * H_];
__device__ __align__(256) __nv_bfloat16 g_ah [(size_t)ROWS * H_];
__device__ __align__(256) __nv_bfloat16 g_al [(size_t)ROWS * H_];
__device__ __align__(256) float         g_t1 [(size_t)ROWS * H_];
__device__ __align__(256) __nv_bfloat16 g_f1h[(size_t)ROWS * 4 * H_];
__device__ __align__(256) __nv_bfloat16 g_f1l[(size_t)ROWS * 4 * H_];
// weights (bf16 pairs)
__device__ __align__(256) __nv_bfloat16 g_wqkvh[LAYERS * 3 * H_ * H_], g_wqkvl[LAYERS * 3 * H_ * H_];
__device__ __align__(256) __nv_bfloat16 g_woh  [LAYERS * H_ * H_],     g_wol  [LAYERS * H_ * H_];
__device__ __align__(256) __nv_bfloat16 g_w1h  [LAYERS * 4 * H_ * H_], g_w1l  [LAYERS * 4 * H_ * H_];
__device__ __align__(256) __nv_bfloat16 g_w2h  [LAYERS * 4 * H_ * H_], g_w2l  [LAYERS * 4 * H_ * H_];
__device__ __align__(256) __nv_bfloat16 g_wmh  [(LAYERS-1) * H_ * 3 * H_], g_wml[(LAYERS-1) * H_ * 3 * H_];
// graph / mixprop
__device__ float g_m1 [C_ * H_];
__device__ float g_m2 [C_ * H_];
__device__ float g_adj[C_ * C_];
__device__ __align__(256) float         g_ho [(size_t)BS * C_ * NCLS * 3 * H_];
__device__ __align__(256) __nv_bfloat16 g_hoh[(size_t)BS * C_ * NCLS * 3 * H_];
__device__ __align__(256) __nv_bfloat16 g_hol[(size_t)BS * C_ * NCLS * 3 * H_];
__device__ __align__(256) float g_mpo[(size_t)BS * C_ * NCLS * H_];
__device__ __align__(256) float g_z  [(size_t)BS * C_ * NCLS * H_];
__device__ float g_d1 [BS * H_];

// ================= HMMA GEMM (bf16x3, mma.sync, 2-stage) =================
// C[M,N] = A[M,K] @ B[N,K]^T + bias.  mode 0: fp32 out; mode 1: relu + bf16 pair.
// grid = (N/128, M/128), 256 threads. M,N %128 == 0, K %32 == 0.
// 2-stage double buffer: 81,920 B SMEM -> 2 CTAs/SM (critical for overlap).
#define ASTR    40                        // bf16 row pitch (80B) — conflict-free
#define TILE_B  (128 * ASTR * 2)          // 10240 bytes per buffer
#define STAGE_B (4 * TILE_B)              // Ah, Al, Bh, Bl
#define SMEM_GEMM_BYTES (2 * STAGE_B)     // 81920
#define OFF_AH  0
#define OFF_AL  TILE_B
#define OFF_BH  (2 * TILE_B)
#define OFF_BL  (3 * TILE_B)

__global__ __launch_bounds__(256) void gemm_bf3_kernel(
    const __nv_bfloat16* __restrict__ Ah, const __nv_bfloat16* __restrict__ Al,
    const __nv_bfloat16* __restrict__ Bh, const __nv_bfloat16* __restrict__ Bl,
    const float* __restrict__ bias,
    float* __restrict__ Cf, __nv_bfloat16* __restrict__ Ch, __nv_bfloat16* __restrict__ Cl,
    int M, int N, int K, int mode)
{
    extern __shared__ char smem[];
    uint32_t sb = smem_u32(smem);
    int tid = threadIdx.x;
    int lane = tid & 31;
    int w = tid >> 5;
    int wm = w >> 2;            // 0..1
    int wn = w & 3;             // 0..3
    int m0 = blockIdx.y * 128, n0 = blockIdx.x * 128;

    float acc[4][4][4];
    #pragma unroll
    for (int i = 0; i < 4; i++)
        #pragma unroll
        for (int j = 0; j < 4; j++)
            #pragma unroll
            for (int k = 0; k < 4; k++) acc[i][j][k] = 0.f;

    int nch = K >> 5;

    // ---- stage loader: 128 rows x 32 bf16 per buffer; 2 x 16B per thread ----
    #define ISSUE_STAGE(cidx) do {                                               \
        int _s = (cidx) & 1; int _kc = (cidx) << 5;                              \
        uint32_t _base = sb + _s * STAGE_B;                                      \
        _Pragma("unroll")                                                        \
        for (int _i = 0; _i < 2; _i++) {                                         \
            int _id = tid + _i * 256;                                            \
            int _r = _id >> 2;                                                   \
            int _cc = (_id & 3) << 3;                                            \
            uint32_t _do = (uint32_t)(_r * (ASTR * 2) + _cc * 2);                \
            size_t _ga = (size_t)(m0 + _r) * K + _kc + _cc;                      \
            size_t _gb = (size_t)(n0 + _r) * K + _kc + _cc;                      \
            cp16(_base + OFF_AH + _do, Ah + _ga);                                \
            cp16(_base + OFF_AL + _do, Al + _ga);                                \
            cp16(_base + OFF_BH + _do, Bh + _gb);                                \
            cp16(_base + OFF_BL + _do, Bl + _gb);                                \
        }                                                                        \
        asm volatile("cp.async.commit_group;" ::: "memory");                     \
    } while (0)

    ISSUE_STAGE(0);

    for (int c = 0; c < nch; c++) {
        if (c + 1 < nch) {
            ISSUE_STAGE(c + 1);
            asm volatile("cp.async.wait_group 1;" ::: "memory");
        } else {
            asm volatile("cp.async.wait_group 0;" ::: "memory");
        }
        __syncthreads();

        uint32_t base = sb + (c & 1) * STAGE_B;
        #pragma unroll
        for (int ks = 0; ks < 2; ks++) {
            uint32_t ah[4][4], al[4][4], bh[4][2], bl[4][2];
            int arow = wm * 64 + (lane & 15);
            int akc  = ks * 16 + (lane >> 4) * 8;
            #pragma unroll
            for (int mf = 0; mf < 4; mf++) {
                uint32_t off = (uint32_t)(((arow + mf * 16) * ASTR + akc) * 2);
                ldsm4(ah[mf], base + OFF_AH + off);
                ldsm4(al[mf], base + OFF_AL + off);
            }
            int brow = wn * 32 + (lane & 7);
            int bkc  = ks * 16 + (((lane & 15) >> 3)) * 8;
            #pragma unroll
            for (int nf = 0; nf < 4; nf++) {
                uint32_t off = (uint32_t)(((brow + nf * 8) * ASTR + bkc) * 2);
                ldsm2(bh[nf], base + OFF_BH + off);
                ldsm2(bl[nf], base + OFF_BL + off);
            }
            // pass-reordered MMAs: per-acc order unchanged (hh, hl, lh) but
            // back-to-back MMAs never share an accumulator (RAW spacing 16)
            #pragma unroll
            for (int mf = 0; mf < 4; mf++)
                #pragma unroll
                for (int nf = 0; nf < 4; nf++)
                    mma16816(acc[mf][nf], ah[mf], bh[nf]);
            #pragma unroll
            for (int mf = 0; mf < 4; mf++)
                #pragma unroll
                for (int nf = 0; nf < 4; nf++)
                    mma16816(acc[mf][nf], ah[mf], bl[nf]);
            #pragma unroll
            for (int mf = 0; mf < 4; mf++)
                #pragma unroll
                for (int nf = 0; nf < 4; nf++)
                    mma16816(acc[mf][nf], al[mf], bh[nf]);
        }
        __syncthreads();
    }

    // ---- epilogue ----
    int rbase = m0 + wm * 64 + (lane >> 2);
    int cbase = n0 + wn * 32 + (lane & 3) * 2;
    #pragma unroll
    for (int mf = 0; mf < 4; mf++) {
        #pragma unroll
        for (int nf = 0; nf < 4; nf++) {
            int r = rbase + mf * 16;
            int cc = cbase + nf * 8;
            float b0 = bias[cc], b1 = bias[cc + 1];
            if (mode == 0) {
                float2 v0 = { acc[mf][nf][0] + b0, acc[mf][nf][1] + b1 };
                float2 v1 = { acc[mf][nf][2] + b0, acc[mf][nf][3] + b1 };
                *(float2*)(Cf + (size_t)r * N + cc)       = v0;
                *(float2*)(Cf + (size_t)(r + 8) * N + cc) = v1;
            } else {
                float v0 = fmaxf(acc[mf][nf][0] + b0, 0.f);
                float v1 = fmaxf(acc[mf][nf][1] + b1, 0.f);
                float v2 = fmaxf(acc[mf][nf][2] + b0, 0.f);
                float v3 = fmaxf(acc[mf][nf][3] + b1, 0.f);
                __nv_bfloat16 h0, l0, h1, l1, h2, l2, h3, l3;
                split_bf16(v0, h0, l0); split_bf16(v1, h1, l1);
                split_bf16(v2, h2, l2); split_bf16(v3, h3, l3);
                __nv_bfloat162 hh0; hh0.x = h0; hh0.y = h1;
                __nv_bfloat162 ll0; ll0.x = l0; ll0.y = l1;
                __nv_bfloat162 hh1; hh1.x = h2; hh1.y = h3;
                __nv_bfloat162 ll1; ll1.x = l2; ll1.y = l3;
                *(__nv_bfloat162*)(Ch + (size_t)r * N + cc)       = hh0;
                *(__nv_bfloat162*)(Cl + (size_t)r * N + cc)       = ll0;
                *(__nv_bfloat162*)(Ch + (size_t)(r + 8) * N + cc) = hh1;
                *(__nv_bfloat162*)(Cl + (size_t)(r + 8) * N + cc) = ll1;
            }
        }
    }
}

// ================= misc kernels =================
__global__ __launch_bounds__(256) void conv_pair_kernel(
    const float* __restrict__ s, __nv_bfloat16* __restrict__ hi,
    __nv_bfloat16* __restrict__ lo, int n)
{
    int i = blockIdx.x * 256 + threadIdx.x;
    if (i < n) {
        __nv_bfloat16 h, l;
        split_bf16(s[i], h, l);
        hi[i] = h; lo[i] = l;
    }
}

__global__ __launch_bounds__(256) void embed_kernel(
    const float* __restrict__ x, const float* __restrict__ Wfc,
    const float* __restrict__ bfc, const float* __restrict__ cls,
    const float* __restrict__ pos)
{
    int row = blockIdx.x;
    int l  = row % L_;
    int bc = row / L_;
    int c  = bc % C_;
    int b  = bc / C_;
    int t  = threadIdx.x;

    __shared__ float xs[IN_];
    float val;
    if (l < T_) {
        if (t < IN_) xs[t] = x[(((size_t)b * T_ + l) * C_ + c) * IN_ + t];
        __syncthreads();
        float s = bfc[t];
        #pragma unroll
        for (int i = 0; i < IN_; i++) s += xs[i] * Wfc[t * IN_ + i];
        val = s;
    } else {
        val = cls[((l - T_) * C_ + c) * H_ + t];
    }
    val += pos[((size_t)l * C_ + c) * H_ + t];
    size_t o = (size_t)row * H_ + t;
    g_h[o] = val;
    __nv_bfloat16 h, lo_;
    split_bf16(val, h, lo_);
    g_hh[o] = h; g_hl[o] = lo_;
}

__global__ __launch_bounds__(256) void graph_kernel(
    const float* __restrict__ emb1, const float* __restrict__ emb2,
    const float* __restrict__ Wl1, const float* __restrict__ bl1,
    const float* __restrict__ Wl2, const float* __restrict__ bl2)
{
    int t = threadIdx.x;
    for (int i = 0; i < C_; i++) {
        float s1 = bl1[t], s2 = bl2[t];
        for (int k = 0; k < H_; k++) {
            s1 += emb1[i * H_ + k] * Wl1[t * H_ + k];
            s2 += emb2[i * H_ + k] * Wl2[t * H_ + k];
        }
        g_m1[i * H_ + t] = tanhf(s1);
        g_m2[i * H_ + t] = tanhf(s2);
    }
    __syncthreads();

    __shared__ float adj[C_][C_];
    __shared__ float rsum[C_];
    int v = t >> 4, w = t & 15;
    float s = 0.f;
    for (int j = 0; j < H_; j++)
        s += g_m1[v * H_ + j] * g_m2[w * H_ + j]
           - g_m2[v * H_ + j] * g_m1[w * H_ + j];
    float gv = fmaxf(tanhf(s), 0.f);
    if (v == w) gv += 1.0f;
    adj[v][w] = gv;
    __syncthreads();
    if (t < C_) {
        float r = 0.f;
        for (int k = 0; k < C_; k++) r += adj[t][k];
        rsum[t] = r;
    }
    __syncthreads();
    g_adj[t] = adj[v][w] / rsum[v];
}

// ================= attention (3-phase, SMEM scores) =================
// block per (seq, head), 256 threads. 84 KB SMEM -> 2 CTAs/SM.
#define QP 36          // Q/K/V row pitch (floats) — float4-aligned, conflict-free
#define SP 101         // score row pitch — conflict-free column access
#define ATT_SMEM ((3 * L_ * QP + L_ * SP + L_) * 4)   // 84000 bytes

__global__ __launch_bounds__(256) void attn_kernel(const float* __restrict__ qkv)
{
    extern __shared__ float asmem[];
    float* Qs  = asmem;                  // [L_][QP]
    float* Ks  = Qs + L_ * QP;
    float* Vs  = Ks + L_ * QP;
    float* Ss  = Vs + L_ * QP;           // [L_][SP]
    float* inv = Ss + L_ * SP;           // [L_]

    int bh = blockIdx.x;
    int b = bh >> 3, h = bh & 7;
    int tid = threadIdx.x;
    int lane = tid & 31, w = tid >> 5;

    const float* base = qkv + (size_t)b * L_ * (3 * H_) + h * DH_;
    for (int idx = tid; idx < L_ * DH_; idx += 256) {
        int l = idx >> 5, d = idx & 31;
        const float* r = base + (size_t)l * (3 * H_) + d;
        Qs[l * QP + d] = r[0];
        Ks[l * QP + d] = r[H_];
        Vs[l * QP + d] = r[2 * H_];
    }
    __syncthreads();

    // ---- phase 1: scores. warp w: i-half (w>>2), j-block jb = w&3 ----
    {
        int jb = w & 3;
        int j = jb * 32 + lane;
        float kr[32];
        if (j < L_) {
            #pragma unroll
            for (int dc = 0; dc < 8; dc++) {
                float4 kv = *(const float4*)(Ks + j * QP + dc * 4);
                kr[dc * 4 + 0] = kv.x; kr[dc * 4 + 1] = kv.y;
                kr[dc * 4 + 2] = kv.z; kr[dc * 4 + 3] = kv.w;
            }
        }
        int i0 = (w >> 2) * 50;
        for (int i = i0; i < i0 + 50; i++) {
            if (i < T_ && jb * 32 > i) continue;   // whole j-block masked
            float a0 = 0.f, a1 = 0.f, a2 = 0.f, a3 = 0.f;
            #pragma unroll
            for (int dc = 0; dc < 8; dc++) {
                float4 qv = *(const float4*)(Qs + i * QP + dc * 4);
                a0 += qv.x * kr[dc * 4 + 0];
                a1 += qv.y * kr[dc * 4 + 1];
                a2 += qv.z * kr[dc * 4 + 2];
                a3 += qv.w * kr[dc * 4 + 3];
            }
            if (j < L_)
                Ss[i * SP + j] = (a0 + a1 + a2 + a3) * 0.17677669529663687f;
        }
    }
    __syncthreads();

    // ---- phase 2: softmax per row (exp stored unnormalized; 1/sum kept) ----
    if (tid < L_) {
        int i = tid;
        int jmax = (i >= T_) ? L_ : i + 1;
        float m = -1e30f;
        for (int j = 0; j < jmax; j++) m = fmaxf(m, Ss[i * SP + j]);
        float sum = 0.f;
        for (int j = 0; j < jmax; j++) {
            float p = __expf(Ss[i * SP + j] - m);
            Ss[i * SP + j] = p;
            sum += p;
        }
        for (int j = jmax; j < L_; j++) Ss[i * SP + j] = 0.f;
        inv[i] = 1.f / sum;
    }
    __syncthreads();

    // ---- phase 3: O = P V. warp w: i-block ib = w&3, d-chunk (w>>2)*16 ----
    {
        int ib = w & 3;
        int i = ib * 32 + lane;
        int dc0 = (w >> 2) * 16;
        float acc[16];
        #pragma unroll
        for (int t = 0; t < 16; t++) acc[t] = 0.f;
        int jmaxw = (ib < 3) ? (ib * 32 + 32) : L_;
        for (int j = 0; j < jmaxw; j++) {
            float p = (i < L_) ? Ss[i * SP + j] : 0.f;
            #pragma unroll
            for (int q4 = 0; q4 < 4; q4++) {
                float4 vv = *(const float4*)(Vs + j * QP + dc0 + q4 * 4);
                acc[q4 * 4 + 0] += p * vv.x;
                acc[q4 * 4 + 1] += p * vv.y;
                acc[q4 * 4 + 2] += p * vv.z;
                acc[q4 * 4 + 3] += p * vv.w;
            }
        }
        if (i < L_) {
            float sc = inv[i];
            size_t o = ((size_t)b * L_ + i) * H_ + h * DH_ + dc0;
            #pragma unroll
            for (int t = 0; t < 16; t += 2) {
                float v0 = acc[t] * sc, v1 = acc[t + 1] * sc;
                __nv_bfloat16 h0, l0, h1, l1;
                split_bf16(v0, h0, l0);
                split_bf16(v1, h1, l1);
                __nv_bfloat162 hh; hh.x = h0; hh.y = h1;
                __nv_bfloat162 ll; ll.x = l0; ll.y = l1;
                *(__nv_bfloat162*)(g_ah + o + t) = hh;
                *(__nv_bfloat162*)(g_al + o + t) = ll;
            }
        }
    }
}

// fused residual-add + LayerNorm; writes fp32 h and bf16 pair
__global__ __launch_bounds__(256) void add_ln_kernel(
    const float* __restrict__ xin,
    const float* __restrict__ g, const float* __restrict__ bt)
{
    int row = blockIdx.x, t = threadIdx.x;
    size_t base = (size_t)row * H_;
    float v = g_h[base + t] + xin[base + t];

    __shared__ float ws[8];
    float s = v;
    #pragma unroll
    for (int o = 16; o > 0; o >>= 1) s += __shfl_xor_sync(0xffffffffu, s, o);
    if ((t & 31) == 0) ws[t >> 5] = s;
    __syncthreads();
    float tot = 0.f;
    #pragma unroll
    for (int i = 0; i < 8; i++) tot += ws[i];
    float mean = tot * (1.0f / H_);
    float d = v - mean;
    __syncthreads();

    float q = d * d;
    #pragma unroll
    for (int o = 16; o > 0; o >>= 1) q += __shfl_xor_sync(0xffffffffu, q, o);
    if ((t & 31) == 0) ws[t >> 5] = q;
    __syncthreads();
    float qt = 0.f;
    #pragma unroll
    for (int i = 0; i < 8; i++) qt += ws[i];
    float var = qt * (1.0f / H_);

    float out = d * rsqrtf(var + EPS_) * g[t] + bt[t];
    g_h[base + t] = out;
    __nv_bfloat16 hh, ll;
    split_bf16(out, hh, ll);
    g_hh[base + t] = hh; g_hl[base + t] = ll;
}

// ---------------- mixprop helpers -----------------
__global__ __launch_bounds__(256) void mp_gather_kernel()
{
    int idx = blockIdx.x * 256 + threadIdx.x;
    int hd = idx & 255;
    int r  = idx >> 8;
    int l  = r & 3;
    int nw = r >> 2;
    g_ho[(size_t)r * (3 * H_) + hd] = g_h[((size_t)nw * L_ + T_ + l) * H_ + hd];
}

__global__ __launch_bounds__(256) void mp_prop_kernel(int depth)
{
    int idx = blockIdx.x * 256 + threadIdx.x;
    int hd = idx & 255;
    int r  = idx >> 8;
    int l  = r & 3;
    int v  = (r >> 2) & 15;
    int n  = r >> 6;
    float s = 0.f;
    #pragma unroll
    for (int w = 0; w < C_; w++)
        s += g_adj[v * C_ + w] *
             g_ho[(size_t)(((n * C_ + w) << 2) + l) * (3 * H_) + (depth - 1) * H_ + hd];
    g_ho[(size_t)r * (3 * H_) + depth * H_ + hd] = s;
}

__global__ __launch_bounds__(256) void mp_scatter_kernel()
{
    int idx = blockIdx.x * 256 + threadIdx.x;
    int o  = idx & 255;
    int r  = idx >> 8;
    int l  = r & 3;
    int nw = r >> 2;
    float v = g_mpo[(size_t)r * H_ + o];
    size_t dst = ((size_t)nw * L_ + T_ + l) * H_ + o;
    g_h[dst] = v;
    __nv_bfloat16 hh, ll;
    split_bf16(v, hh, ll);
    g_hh[dst] = hh; g_hl[dst] = ll;
}

// ---------------- head ----------------
__global__ __launch_bounds__(256) void tanh_gather_kernel()
{
    int idx = blockIdx.x * 256 + threadIdx.x;
    int hd = idx & 255;
    int r  = idx >> 8;
    int n  = r & 3;
    int c  = (r >> 2) & 15;
    int b  = r >> 6;
    g_z[idx] = tanhf(g_h[(((size_t)(b * C_ + c)) * L_ + T_ + n) * H_ + hd]);
}

// 64 blocks (per batch), 512 threads; z row cached in SMEM (64KB)
__global__ __launch_bounds__(512) void head_gemm_kernel(
    const float* __restrict__ Wd1, const float* __restrict__ bd1)
{
    extern __shared__ float zs[];
    int b = blockIdx.x;
    int tid = threadIdx.x;
    for (int i = tid; i < C_ * NCLS * H_; i += 512)
        zs[i] = g_z[(size_t)b * (C_ * NCLS * H_) + i];
    __syncthreads();
    int wid = tid >> 5, lane = tid & 31;
    for (int o = wid; o < H_; o += 16) {
        const float* w = Wd1 + (size_t)o * (C_ * NCLS * H_);
        float s = 0.f;
        for (int k = lane; k < C_ * NCLS * H_; k += 32)
            s += zs[k] * w[k];
        #pragma unroll
        for (int off = 16; off > 0; off >>= 1)
            s += __shfl_xor_sync(0xffffffffu, s, off);
        if (lane == 0) g_d1[b * H_ + o] = s + bd1[o];
    }
}

__global__ __launch_bounds__(256) void head_kernel(
    const float* __restrict__ Wd2, const float* __restrict__ bd2,
    float* __restrict__ out)
{
    int b = blockIdx.x, t = threadIdx.x;
    float x = g_d1[b * H_ + t];
    float gl = 0.5f * x * (1.0f + erff(x * 0.70710678118654752f));
    float v = gl * Wd2[t];
    #pragma unroll
    for (int o = 16; o > 0; o >>= 1) v += __shfl_xor_sync(0xffffffffu, v, o);
    __shared__ float ws[8];
    if ((t & 31) == 0) ws[t >> 5] = v;
    __syncthreads();
    if (t == 0) {
        float s = 0.f;
        #pragma unroll
        for (int i = 0; i < 8; i++) s += ws[i];
        out[b] = s + bd2[0];
    }
}

// ---------------- host ----------------
static float* dev_ptr(const void* symbol)
{
    void* p = nullptr;
    cudaGetSymbolAddress(&p, symbol);
    return (float*)p;
}
static __nv_bfloat16* dev_ptr_b(const void* symbol)
{
    void* p = nullptr;
    cudaGetSymbolAddress(&p, symbol);
    return (__nv_bfloat16*)p;
}

extern "C" void kernel_launch(void* const* d_in, const int* in_sizes, int n_in,
                              void* d_out, int out_size)
{
    const float* x        = (const float*)d_in[0];
    const float* Wfc      = (const float*)d_in[3];
    const float* bfc      = (const float*)d_in[4];
    const float* cls_tok  = (const float*)d_in[5];
    const float* pos_emb  = (const float*)d_in[6];
    const float* emb1     = (const float*)d_in[7];
    const float* emb2     = (const float*)d_in[8];
    const float* Wl1      = (const float*)d_in[9];
    const float* bl1      = (const float*)d_in[10];
    const float* Wl2      = (const float*)d_in[11];
    const float* bl2      = (const float*)d_in[12];
    const float* Wqkv     = (const float*)d_in[13];
    const float* bqkv     = (const float*)d_in[14];
    const float* Wo       = (const float*)d_in[15];
    const float* bo       = (const float*)d_in[16];
    const float* W1       = (const float*)d_in[17];
    const float* b1       = (const float*)d_in[18];
    const float* W2       = (const float*)d_in[19];
    const float* b2       = (const float*)d_in[20];
    const float* ln1g     = (const float*)d_in[21];
    const float* ln1b     = (const float*)d_in[22];
    const float* ln2g     = (const float*)d_in[23];
    const float* ln2b     = (const float*)d_in[24];
    const float* Wmlp     = (const float*)d_in[25];
    const float* bmlp     = (const float*)d_in[26];
    const float* Wd1      = (const float*)d_in[27];
    const float* bd1      = (const float*)d_in[28];
    const float* Wd2      = (const float*)d_in[29];
    const float* bd2      = (const float*)d_in[30];
    float* out = (float*)d_out;

    static bool inited = false;
    static float *p_h, *p_qkv, *p_t1, *p_mpo, *p_ho;
    static __nv_bfloat16 *p_hh, *p_hl, *p_ah, *p_al, *p_f1h, *p_f1l;
    static __nv_bfloat16 *p_wqkvh, *p_wqkvl, *p_woh, *p_wol, *p_w1h, *p_w1l,
                         *p_w2h, *p_w2l, *p_wmh, *p_wml, *p_hoh, *p_hol;
    if (!inited) {
        cudaFuncSetAttribute(gemm_bf3_kernel,
            cudaFuncAttributeMaxDynamicSharedMemorySize, SMEM_GEMM_BYTES);
        cudaFuncSetAttribute(attn_kernel,
            cudaFuncAttributeMaxDynamicSharedMemorySize, ATT_SMEM);
        cudaFuncSetAttribute(head_gemm_kernel,
            cudaFuncAttributeMaxDynamicSharedMemorySize, C_ * NCLS * H_ * 4);
        p_h = dev_ptr(g_h); p_qkv = dev_ptr(g_qkv); p_t1 = dev_ptr(g_t1);
        p_mpo = dev_ptr(g_mpo); p_ho = dev_ptr(g_ho);
        p_hh = dev_ptr_b(g_hh); p_hl = dev_ptr_b(g_hl);
        p_ah = dev_ptr_b(g_ah); p_al = dev_ptr_b(g_al);
        p_f1h = dev_ptr_b(g_f1h); p_f1l = dev_ptr_b(g_f1l);
        p_wqkvh = dev_ptr_b(g_wqkvh); p_wqkvl = dev_ptr_b(g_wqkvl);
        p_woh = dev_ptr_b(g_woh); p_wol = dev_ptr_b(g_wol);
        p_w1h = dev_ptr_b(g_w1h); p_w1l = dev_ptr_b(g_w1l);
        p_w2h = dev_ptr_b(g_w2h); p_w2l = dev_ptr_b(g_w2l);
        p_wmh = dev_ptr_b(g_wmh); p_wml = dev_ptr_b(g_wml);
        p_hoh = dev_ptr_b(g_hoh); p_hol = dev_ptr_b(g_hol);
        inited = true;
    }

    // weight conversion (fp32 -> bf16 hi/lo)
    conv_pair_kernel<<<(LAYERS * 3 * H_ * H_) / 256, 256>>>(Wqkv, p_wqkvh, p_wqkvl, LAYERS * 3 * H_ * H_);
    conv_pair_kernel<<<(LAYERS * H_ * H_) / 256, 256>>>(Wo, p_woh, p_wol, LAYERS * H_ * H_);
    conv_pair_kernel<<<(LAYERS * 4 * H_ * H_) / 256, 256>>>(W1, p_w1h, p_w1l, LAYERS * 4 * H_ * H_);
    conv_pair_kernel<<<(LAYERS * 4 * H_ * H_) / 256, 256>>>(W2, p_w2h, p_w2l, LAYERS * 4 * H_ * H_);
    conv_pair_kernel<<<((LAYERS - 1) * H_ * 3 * H_) / 256, 256>>>(Wmlp, p_wmh, p_wml, (LAYERS - 1) * H_ * 3 * H_);

    graph_kernel<<<1, 256>>>(emb1, emb2, Wl1, bl1, Wl2, bl2);
    embed_kernel<<<ROWS, 256>>>(x, Wfc, bfc, cls_tok, pos_emb);

    const int MP_THREADS = BS * C_ * NCLS * H_;   // 1,048,576
    const int HO_N = BS * C_ * NCLS * 3 * H_;     // 3,145,728

    for (int l = 0; l < LAYERS; l++) {
        if (l > 0) {
            mp_gather_kernel<<<MP_THREADS / 256, 256>>>();
            mp_prop_kernel<<<MP_THREADS / 256, 256>>>(1);
            mp_prop_kernel<<<MP_THREADS / 256, 256>>>(2);
            conv_pair_kernel<<<HO_N / 256, 256>>>(p_ho, p_hoh, p_hol, HO_N);
            gemm_bf3_kernel<<<dim3(2, 32), 256, SMEM_GEMM_BYTES>>>(
                p_hoh, p_hol,
                p_wmh + (size_t)(l - 1) * H_ * 3 * H_, p_wml + (size_t)(l - 1) * H_ * 3 * H_,
                bmlp + (size_t)(l - 1) * H_,
                p_mpo, nullptr, nullptr,
                BS * C_ * NCLS, H_, 3 * H_, 0);
            mp_scatter_kernel<<<MP_THREADS / 256, 256>>>();
        }

        // QKV projection
        gemm_bf3_kernel<<<dim3(6, ROWS / 128), 256, SMEM_GEMM_BYTES>>>(
            p_hh, p_hl,
            p_wqkvh + (size_t)l * 3 * H_ * H_, p_wqkvl + (size_t)l * 3 * H_ * H_,
            bqkv + (size_t)l * 3 * H_,
            p_qkv, nullptr, nullptr, ROWS, 3 * H_, H_, 0);

        attn_kernel<<<BP * NH_, 256, ATT_SMEM>>>(p_qkv);

        // output projection -> g_t1
        gemm_bf3_kernel<<<dim3(2, ROWS / 128), 256, SMEM_GEMM_BYTES>>>(
            p_ah, p_al,
            p_woh + (size_t)l * H_ * H_, p_wol + (size_t)l * H_ * H_,
            bo + (size_t)l * H_,
            p_t1, nullptr, nullptr, ROWS, H_, H_, 0);

        add_ln_kernel<<<ROWS, 256>>>(p_t1, ln1g + l * H_, ln1b + l * H_);

        // FFN
        gemm_bf3_kernel<<<dim3(8, ROWS / 128), 256, SMEM_GEMM_BYTES>>>(
            p_hh, p_hl,
            p_w1h + (size_t)l * 4 * H_ * H_, p_w1l + (size_t)l * 4 * H_ * H_,
            b1 + (size_t)l * 4 * H_,
            nullptr, p_f1h, p_f1l, ROWS, 4 * H_, H_, 1);

        gemm_bf3_kernel<<<dim3(2, ROWS / 128), 256, SMEM_GEMM_BYTES>>>(
            p_f1h, p_f1l,
            p_w2h + (size_t)l * 4 * H_ * H_, p_w2l + (size_t)l * 4 * H_ * H_,
            b2 + (size_t)l * H_,
            p_t1, nullptr, nullptr, ROWS, H_, 4 * H_, 0);

        add_ln_kernel<<<ROWS, 256>>>(p_t1, ln2g + l * H_, ln2b + l * H_);
    }

    tanh_gather_kernel<<<MP_THREADS / 256, 256>>>();
    head_gemm_kernel<<<BS, 512, C_ * NCLS * H_ * 4>>>(Wd1, bd1);
    head_kernel<<<BS, 256>>>(Wd2, bd2, out);
}

// round 10
// speedup vs baseline: 1.2542x; 1.0939x over previous
#include <cuda_runtime.h>
#include <cuda_bf16.h>
#include <math.h>
#include <stdint.h>

// ---------------- model constants ----------------
#define BS    64
#define T_    96
#define C_    16
#define IN_   16
#define H_    256
#define NH_   8
#define DH_   32
#define NCLS  4
#define L_    100          // T + NCLS
#define LAYERS 4
#define BP    (BS * C_)    // 1024 sequences
#define ROWS  (BP * L_)    // 102400 token rows
#define EPS_  1e-5f

// ================= low-level helpers =================
__device__ __forceinline__ uint32_t smem_u32(const void* p) {
    uint32_t a;
    asm("{ .reg .u64 t; cvta.to.shared.u64 t, %1; cvt.u32.u64 %0, t; }"
        : "=r"(a) : "l"(p));
    return a;
}
__device__ __forceinline__ void cp16(uint32_t dst, const void* src) {
    asm volatile("cp.async.cg.shared.global [%0], [%1], 16;" :: "r"(dst), "l"(src) : "memory");
}
__device__ __forceinline__ void ldsm4(uint32_t* r, uint32_t addr) {
    asm volatile("ldmatrix.sync.aligned.m8n8.x4.shared.b16 {%0,%1,%2,%3}, [%4];"
        : "=r"(r[0]), "=r"(r[1]), "=r"(r[2]), "=r"(r[3]) : "r"(addr));
}
__device__ __forceinline__ void ldsm2(uint32_t* r, uint32_t addr) {
    asm volatile("ldmatrix.sync.aligned.m8n8.x2.shared.b16 {%0,%1}, [%2];"
        : "=r"(r[0]), "=r"(r[1]) : "r"(addr));
}
__device__ __forceinline__ void mma16816(float* d, const uint32_t* a, const uint32_t* b) {
    asm volatile("mma.sync.aligned.m16n8k16.row.col.f32.bf16.bf16.f32 "
        "{%0,%1,%2,%3}, {%4,%5,%6,%7}, {%8,%9}, {%0,%1,%2,%3};"
        : "+f"(d[0]), "+f"(d[1]), "+f"(d[2]), "+f"(d[3])
        : "r"(a[0]), "r"(a[1]), "r"(a[2]), "r"(a[3]), "r"(b[0]), "r"(b[1]));
}

// ---------------- bf16 split helper ----------------
__device__ __forceinline__ void split_bf16(float v, __nv_bfloat16& hi, __nv_bfloat16& lo) {
    hi = __float2bfloat16(v);
    lo = __float2bfloat16(v - __bfloat162float(hi));
}

// ---------------- scratch (device globals) -------------
__device__ __align__(256) float         g_h  [(size_t)ROWS * H_];
__device__ __align__(256) __nv_bfloat16 g_hh [(size_t)ROWS * H_];
__device__ __align__(256) __nv_bfloat16 g_hl [(size_t)ROWS * H_];
__device__ __align__(256) float         g_qkv[(size_t)ROWS * 3 * H_];
__device__ __align__(256) __nv_bfloat16 g_ah [(size_t)ROWS * H_];
__device__ __align__(256) __nv_bfloat16 g_al [(size_t)ROWS * H_];
__device__ __align__(256) float         g_t1 [(size_t)ROWS * H_];
__device__ __align__(256) __nv_bfloat16 g_f1h[(size_t)ROWS * 4 * H_];
__device__ __align__(256) __nv_bfloat16 g_f1l[(size_t)ROWS * 4 * H_];
// weights (bf16 pairs)
__device__ __align__(256) __nv_bfloat16 g_wqkvh[LAYERS * 3 * H_ * H_], g_wqkvl[LAYERS * 3 * H_ * H_];
__device__ __align__(256) __nv_bfloat16 g_woh  [LAYERS * H_ * H_],     g_wol  [LAYERS * H_ * H_];
__device__ __align__(256) __nv_bfloat16 g_w1h  [LAYERS * 4 * H_ * H_], g_w1l  [LAYERS * 4 * H_ * H_];
__device__ __align__(256) __nv_bfloat16 g_w2h  [LAYERS * 4 * H_ * H_], g_w2l  [LAYERS * 4 * H_ * H_];
__device__ __align__(256) __nv_bfloat16 g_wmh  [(LAYERS-1) * H_ * 3 * H_], g_wml[(LAYERS-1) * H_ * 3 * H_];
// graph / mixprop
__device__ float g_m1 [C_ * H_];
__device__ float g_m2 [C_ * H_];
__device__ float g_adj[C_ * C_];
__device__ __align__(256) __nv_bfloat16 g_hoh[(size_t)BS * C_ * NCLS * 3 * H_];
__device__ __align__(256) __nv_bfloat16 g_hol[(size_t)BS * C_ * NCLS * 3 * H_];
__device__ __align__(256) float g_mpo[(size_t)BS * C_ * NCLS * H_];
__device__ __align__(256) float g_z  [(size_t)BS * C_ * NCLS * H_];
__device__ float g_d1 [BS * H_];

// ================= HMMA GEMM (bf16x3, mma.sync, 2-stage) =================
// Exact round-7 configuration (known-good, 2 CTAs/SM).
#define ASTR    40                        // bf16 row pitch (80B) — conflict-free
#define TILE_B  (128 * ASTR * 2)          // 10240 bytes per buffer
#define STAGE_B (4 * TILE_B)              // Ah, Al, Bh, Bl
#define SMEM_GEMM_BYTES (2 * STAGE_B)     // 81920
#define OFF_AH  0
#define OFF_AL  TILE_B
#define OFF_BH  (2 * TILE_B)
#define OFF_BL  (3 * TILE_B)

__global__ __launch_bounds__(256) void gemm_bf3_kernel(
    const __nv_bfloat16* __restrict__ Ah, const __nv_bfloat16* __restrict__ Al,
    const __nv_bfloat16* __restrict__ Bh, const __nv_bfloat16* __restrict__ Bl,
    const float* __restrict__ bias,
    float* __restrict__ Cf, __nv_bfloat16* __restrict__ Ch, __nv_bfloat16* __restrict__ Cl,
    int M, int N, int K, int mode)
{
    extern __shared__ char smem[];
    uint32_t sb = smem_u32(smem);
    int tid = threadIdx.x;
    int lane = tid & 31;
    int w = tid >> 5;
    int wm = w >> 2;            // 0..1
    int wn = w & 3;             // 0..3
    int m0 = blockIdx.y * 128, n0 = blockIdx.x * 128;

    float acc[4][4][4];
    #pragma unroll
    for (int i = 0; i < 4; i++)
        #pragma unroll
        for (int j = 0; j < 4; j++)
            #pragma unroll
            for (int k = 0; k < 4; k++) acc[i][j][k] = 0.f;

    int nch = K >> 5;

    #define ISSUE_STAGE(cidx) do {                                               \
        int _s = (cidx) & 1; int _kc = (cidx) << 5;                              \
        uint32_t _base = sb + _s * STAGE_B;                                      \
        _Pragma("unroll")                                                        \
        for (int _i = 0; _i < 2; _i++) {                                         \
            int _id = tid + _i * 256;                                            \
            int _r = _id >> 2;                                                   \
            int _cc = (_id & 3) << 3;                                            \
            uint32_t _do = (uint32_t)(_r * (ASTR * 2) + _cc * 2);                \
            size_t _ga = (size_t)(m0 + _r) * K + _kc + _cc;                      \
            size_t _gb = (size_t)(n0 + _r) * K + _kc + _cc;                      \
            cp16(_base + OFF_AH + _do, Ah + _ga);                                \
            cp16(_base + OFF_AL + _do, Al + _ga);                                \
            cp16(_base + OFF_BH + _do, Bh + _gb);                                \
            cp16(_base + OFF_BL + _do, Bl + _gb);                                \
        }                                                                        \
        asm volatile("cp.async.commit_group;" ::: "memory");                     \
    } while (0)

    ISSUE_STAGE(0);

    for (int c = 0; c < nch; c++) {
        if (c + 1 < nch) {
            ISSUE_STAGE(c + 1);
            asm volatile("cp.async.wait_group 1;" ::: "memory");
        } else {
            asm volatile("cp.async.wait_group 0;" ::: "memory");
        }
        __syncthreads();

        uint32_t base = sb + (c & 1) * STAGE_B;
        #pragma unroll
        for (int ks = 0; ks < 2; ks++) {
            uint32_t ah[4][4], al[4][4], bh[4][2], bl[4][2];
            int arow = wm * 64 + (lane & 15);
            int akc  = ks * 16 + (lane >> 4) * 8;
            #pragma unroll
            for (int mf = 0; mf < 4; mf++) {
                uint32_t off = (uint32_t)(((arow + mf * 16) * ASTR + akc) * 2);
                ldsm4(ah[mf], base + OFF_AH + off);
                ldsm4(al[mf], base + OFF_AL + off);
            }
            int brow = wn * 32 + (lane & 7);
            int bkc  = ks * 16 + (((lane & 15) >> 3)) * 8;
            #pragma unroll
            for (int nf = 0; nf < 4; nf++) {
                uint32_t off = (uint32_t)(((brow + nf * 8) * ASTR + bkc) * 2);
                ldsm2(bh[nf], base + OFF_BH + off);
                ldsm2(bl[nf], base + OFF_BL + off);
            }
            #pragma unroll
            for (int mf = 0; mf < 4; mf++)
                #pragma unroll
                for (int nf = 0; nf < 4; nf++) {
                    mma16816(acc[mf][nf], ah[mf], bh[nf]);
                    mma16816(acc[mf][nf], ah[mf], bl[nf]);
                    mma16816(acc[mf][nf], al[mf], bh[nf]);
                }
        }
        __syncthreads();
    }

    // ---- epilogue ----
    int rbase = m0 + wm * 64 + (lane >> 2);
    int cbase = n0 + wn * 32 + (lane & 3) * 2;
    #pragma unroll
    for (int mf = 0; mf < 4; mf++) {
        #pragma unroll
        for (int nf = 0; nf < 4; nf++) {
            int r = rbase + mf * 16;
            int cc = cbase + nf * 8;
            float b0 = bias[cc], b1 = bias[cc + 1];
            if (mode == 0) {
                float2 v0 = { acc[mf][nf][0] + b0, acc[mf][nf][1] + b1 };
                float2 v1 = { acc[mf][nf][2] + b0, acc[mf][nf][3] + b1 };
                *(float2*)(Cf + (size_t)r * N + cc)       = v0;
                *(float2*)(Cf + (size_t)(r + 8) * N + cc) = v1;
            } else {
                float v0 = fmaxf(acc[mf][nf][0] + b0, 0.f);
                float v1 = fmaxf(acc[mf][nf][1] + b1, 0.f);
                float v2 = fmaxf(acc[mf][nf][2] + b0, 0.f);
                float v3 = fmaxf(acc[mf][nf][3] + b1, 0.f);
                __nv_bfloat16 h0, l0, h1, l1, h2, l2, h3, l3;
                split_bf16(v0, h0, l0); split_bf16(v1, h1, l1);
                split_bf16(v2, h2, l2); split_bf16(v3, h3, l3);
                __nv_bfloat162 hh0; hh0.x = h0; hh0.y = h1;
                __nv_bfloat162 ll0; ll0.x = l0; ll0.y = l1;
                __nv_bfloat162 hh1; hh1.x = h2; hh1.y = h3;
                __nv_bfloat162 ll1; ll1.x = l2; ll1.y = l3;
                *(__nv_bfloat162*)(Ch + (size_t)r * N + cc)       = hh0;
                *(__nv_bfloat162*)(Cl + (size_t)r * N + cc)       = ll0;
                *(__nv_bfloat162*)(Ch + (size_t)(r + 8) * N + cc) = hh1;
                *(__nv_bfloat162*)(Cl + (size_t)(r + 8) * N + cc) = ll1;
            }
        }
    }
}

// ================= misc kernels =================
__global__ __launch_bounds__(256) void conv_pair_kernel(
    const float* __restrict__ s, __nv_bfloat16* __restrict__ hi,
    __nv_bfloat16* __restrict__ lo, int n)
{
    int i = blockIdx.x * 256 + threadIdx.x;
    if (i < n) {
        __nv_bfloat16 h, l;
        split_bf16(s[i], h, l);
        hi[i] = h; lo[i] = l;
    }
}

__global__ __launch_bounds__(256) void embed_kernel(
    const float* __restrict__ x, const float* __restrict__ Wfc,
    const float* __restrict__ bfc, const float* __restrict__ cls,
    const float* __restrict__ pos)
{
    int row = blockIdx.x;
    int l  = row % L_;
    int bc = row / L_;
    int c  = bc % C_;
    int b  = bc / C_;
    int t  = threadIdx.x;

    __shared__ float xs[IN_];
    float val;
    if (l < T_) {
        if (t < IN_) xs[t] = x[(((size_t)b * T_ + l) * C_ + c) * IN_ + t];
        __syncthreads();
        float s = bfc[t];
        #pragma unroll
        for (int i = 0; i < IN_; i++) s += xs[i] * Wfc[t * IN_ + i];
        val = s;
    } else {
        val = cls[((l - T_) * C_ + c) * H_ + t];
    }
    val += pos[((size_t)l * C_ + c) * H_ + t];
    size_t o = (size_t)row * H_ + t;
    g_h[o] = val;
    __nv_bfloat16 h, lo_;
    split_bf16(val, h, lo_);
    g_hh[o] = h; g_hl[o] = lo_;
}

__global__ __launch_bounds__(256) void graph_kernel(
    const float* __restrict__ emb1, const float* __restrict__ emb2,
    const float* __restrict__ Wl1, const float* __restrict__ bl1,
    const float* __restrict__ Wl2, const float* __restrict__ bl2)
{
    int t = threadIdx.x;
    for (int i = 0; i < C_; i++) {
        float s1 = bl1[t], s2 = bl2[t];
        for (int k = 0; k < H_; k++) {
            s1 += emb1[i * H_ + k] * Wl1[t * H_ + k];
            s2 += emb2[i * H_ + k] * Wl2[t * H_ + k];
        }
        g_m1[i * H_ + t] = tanhf(s1);
        g_m2[i * H_ + t] = tanhf(s2);
    }
    __syncthreads();

    __shared__ float adj[C_][C_];
    __shared__ float rsum[C_];
    int v = t >> 4, w = t & 15;
    float s = 0.f;
    for (int j = 0; j < H_; j++)
        s += g_m1[v * H_ + j] * g_m2[w * H_ + j]
           - g_m2[v * H_ + j] * g_m1[w * H_ + j];
    float gv = fmaxf(tanhf(s), 0.f);
    if (v == w) gv += 1.0f;
    adj[v][w] = gv;
    __syncthreads();
    if (t < C_) {
        float r = 0.f;
        for (int k = 0; k < C_; k++) r += adj[t][k];
        rsum[t] = r;
    }
    __syncthreads();
    g_adj[t] = adj[v][w] / rsum[v];
}

// ================= attention (online softmax, float4 SMEM) =================
// block per (seq, head), 128 threads, thread i = query row.
__global__ __launch_bounds__(128) void attn_kernel(const float* __restrict__ qkv)
{
    int bh = blockIdx.x;
    int b = bh >> 3;
    int h = bh & 7;
    __shared__ float4 Ks[L_][8];
    __shared__ float4 Vs[L_][8];
    const float* base = qkv + (size_t)b * L_ * (3 * H_) + h * DH_;
    for (int idx = threadIdx.x; idx < L_ * 8; idx += 128) {
        int l = idx >> 3, k4 = idx & 7;
        Ks[l][k4] = *(const float4*)(base + (size_t)l * (3 * H_) + H_     + k4 * 4);
        Vs[l][k4] = *(const float4*)(base + (size_t)l * (3 * H_) + 2 * H_ + k4 * 4);
    }
    __syncthreads();

    int i = threadIdx.x;
    if (i < L_) {
        float4 q[8];
        #pragma unroll
        for (int k4 = 0; k4 < 8; k4++)
            q[k4] = *(const float4*)(base + (size_t)i * (3 * H_) + k4 * 4);

        float m = -1e30f, lsum = 0.f;
        float4 acc[8];
        #pragma unroll
        for (int k4 = 0; k4 < 8; k4++) acc[k4] = make_float4(0.f, 0.f, 0.f, 0.f);

        int jmax = (i >= T_) ? L_ : (i + 1);
        for (int j = 0; j < jmax; j++) {
            float a0 = 0.f, a1 = 0.f, a2 = 0.f, a3 = 0.f;
            #pragma unroll
            for (int k4 = 0; k4 < 8; k4++) {
                float4 kv = Ks[j][k4];
                a0 += q[k4].x * kv.x;
                a1 += q[k4].y * kv.y;
                a2 += q[k4].z * kv.z;
                a3 += q[k4].w * kv.w;
            }
            float s = ((a0 + a1) + (a2 + a3)) * 0.17677669529663687f;
            if (s <= m) {
                float p = __expf(s - m);
                lsum += p;
                #pragma unroll
                for (int k4 = 0; k4 < 8; k4++) {
                    float4 vv = Vs[j][k4];
                    acc[k4].x += p * vv.x;
                    acc[k4].y += p * vv.y;
                    acc[k4].z += p * vv.z;
                    acc[k4].w += p * vv.w;
                }
            } else {
                float sc = __expf(m - s);
                lsum = lsum * sc + 1.f;
                #pragma unroll
                for (int k4 = 0; k4 < 8; k4++) {
                    float4 vv = Vs[j][k4];
                    acc[k4].x = acc[k4].x * sc + vv.x;
                    acc[k4].y = acc[k4].y * sc + vv.y;
                    acc[k4].z = acc[k4].z * sc + vv.z;
                    acc[k4].w = acc[k4].w * sc + vv.w;
                }
                m = s;
            }
        }
        float inv = 1.f / lsum;
        size_t o = ((size_t)b * L_ + i) * H_ + h * DH_;
        #pragma unroll
        for (int k4 = 0; k4 < 8; k4++) {
            float v0 = acc[k4].x * inv, v1 = acc[k4].y * inv;
            float v2 = acc[k4].z * inv, v3 = acc[k4].w * inv;
            __nv_bfloat16 h0, l0, h1, l1, h2, l2, h3, l3;
            split_bf16(v0, h0, l0); split_bf16(v1, h1, l1);
            split_bf16(v2, h2, l2); split_bf16(v3, h3, l3);
            __nv_bfloat162 hh0; hh0.x = h0; hh0.y = h1;
            __nv_bfloat162 ll0; ll0.x = l0; ll0.y = l1;
            __nv_bfloat162 hh1; hh1.x = h2; hh1.y = h3;
            __nv_bfloat162 ll1; ll1.x = l2; ll1.y = l3;
            *(__nv_bfloat162*)(g_ah + o + k4 * 4)     = hh0;
            *(__nv_bfloat162*)(g_al + o + k4 * 4)     = ll0;
            *(__nv_bfloat162*)(g_ah + o + k4 * 4 + 2) = hh1;
            *(__nv_bfloat162*)(g_al + o + k4 * 4 + 2) = ll1;
        }
    }
}

// fused residual-add + LayerNorm; writes fp32 h and bf16 pair
__global__ __launch_bounds__(256) void add_ln_kernel(
    const float* __restrict__ xin,
    const float* __restrict__ g, const float* __restrict__ bt)
{
    int row = blockIdx.x, t = threadIdx.x;
    size_t base = (size_t)row * H_;
    float v = g_h[base + t] + xin[base + t];

    __shared__ float ws[8];
    float s = v;
    #pragma unroll
    for (int o = 16; o > 0; o >>= 1) s += __shfl_xor_sync(0xffffffffu, s, o);
    if ((t & 31) == 0) ws[t >> 5] = s;
    __syncthreads();
    float tot = 0.f;
    #pragma unroll
    for (int i = 0; i < 8; i++) tot += ws[i];
    float mean = tot * (1.0f / H_);
    float d = v - mean;
    __syncthreads();

    float q = d * d;
    #pragma unroll
    for (int o = 16; o > 0; o >>= 1) q += __shfl_xor_sync(0xffffffffu, q, o);
    if ((t & 31) == 0) ws[t >> 5] = q;
    __syncthreads();
    float qt = 0.f;
    #pragma unroll
    for (int i = 0; i < 8; i++) qt += ws[i];
    float var = qt * (1.0f / H_);

    float out = d * rsqrtf(var + EPS_) * g[t] + bt[t];
    g_h[base + t] = out;
    __nv_bfloat16 hh, ll;
    split_bf16(out, hh, ll);
    g_hh[base + t] = hh; g_hl[base + t] = ll;
}

// ---------------- fused mixprop (gather + 2 prop depths + bf16 pair out) ---
// block = (n, l): n = blockIdx.x >> 2, l = blockIdx.x & 3. 256 threads (hd).
__global__ __launch_bounds__(256) void mp_fused_kernel()
{
    __shared__ float s0[C_ * H_];     // depth-0 rows [w][hd]
    __shared__ float s1[C_ * H_];     // depth-1 rows [v][hd]
    __shared__ float adjs[C_ * C_];

    int n = blockIdx.x >> 2;
    int l = blockIdx.x & 3;
    int t = threadIdx.x;
    adjs[t] = g_adj[t];

    #pragma unroll
    for (int w = 0; w < C_; w++) {
        float v = g_h[(((size_t)(n * C_ + w)) * L_ + T_ + l) * H_ + t];
        s0[w * H_ + t] = v;
        size_t r = (size_t)((n * C_ + w) * NCLS + l) * (3 * H_);
        __nv_bfloat16 hh, ll;
        split_bf16(v, hh, ll);
        g_hoh[r + t] = hh; g_hol[r + t] = ll;
    }
    __syncthreads();

    #pragma unroll
    for (int v = 0; v < C_; v++) {
        float s = 0.f;
        #pragma unroll
        for (int w = 0; w < C_; w++)
            s += adjs[v * C_ + w] * s0[w * H_ + t];
        s1[v * H_ + t] = s;
        size_t r = (size_t)((n * C_ + v) * NCLS + l) * (3 * H_) + H_;
        __nv_bfloat16 hh, ll;
        split_bf16(s, hh, ll);
        g_hoh[r + t] = hh; g_hol[r + t] = ll;
    }
    __syncthreads();

    #pragma unroll
    for (int v = 0; v < C_; v++) {
        float s = 0.f;
        #pragma unroll
        for (int w = 0; w < C_; w++)
            s += adjs[v * C_ + w] * s1[w * H_ + t];
        size_t r = (size_t)((n * C_ + v) * NCLS + l) * (3 * H_) + 2 * H_;
        __nv_bfloat16 hh, ll;
        split_bf16(s, hh, ll);
        g_hoh[r + t] = hh; g_hol[r + t] = ll;
    }
}

__global__ __launch_bounds__(256) void mp_scatter_kernel()
{
    int idx = blockIdx.x * 256 + threadIdx.x;
    int o  = idx & 255;
    int r  = idx >> 8;
    int l  = r & 3;
    int nw = r >> 2;
    float v = g_mpo[(size_t)r * H_ + o];
    size_t dst = ((size_t)nw * L_ + T_ + l) * H_ + o;
    g_h[dst] = v;
    __nv_bfloat16 hh, ll;
    split_bf16(v, hh, ll);
    g_hh[dst] = hh; g_hl[dst] = ll;
}

// ---------------- head ----------------
__global__ __launch_bounds__(256) void tanh_gather_kernel()
{
    int idx = blockIdx.x * 256 + threadIdx.x;
    int hd = idx & 255;
    int r  = idx >> 8;
    int n  = r & 3;
    int c  = (r >> 2) & 15;
    int b  = r >> 6;
    g_z[idx] = tanhf(g_h[(((size_t)(b * C_ + c)) * L_ + T_ + n) * H_ + hd]);
}

// 64 blocks (per batch), 512 threads; z row cached in SMEM (64KB)
__global__ __launch_bounds__(512) void head_gemm_kernel(
    const float* __restrict__ Wd1, const float* __restrict__ bd1)
{
    extern __shared__ float zs[];
    int b = blockIdx.x;
    int tid = threadIdx.x;
    for (int i = tid; i < C_ * NCLS * H_; i += 512)
        zs[i] = g_z[(size_t)b * (C_ * NCLS * H_) + i];
    __syncthreads();
    int wid = tid >> 5, lane = tid & 31;
    for (int o = wid; o < H_; o += 16) {
        const float* w = Wd1 + (size_t)o * (C_ * NCLS * H_);
        float s = 0.f;
        for (int k = lane; k < C_ * NCLS * H_; k += 32)
            s += zs[k] * w[k];
        #pragma unroll
        for (int off = 16; off > 0; off >>= 1)
            s += __shfl_xor_sync(0xffffffffu, s, off);
        if (lane == 0) g_d1[b * H_ + o] = s + bd1[o];
    }
}

__global__ __launch_bounds__(256) void head_kernel(
    const float* __restrict__ Wd2, const float* __restrict__ bd2,
    float* __restrict__ out)
{
    int b = blockIdx.x, t = threadIdx.x;
    float x = g_d1[b * H_ + t];
    float gl = 0.5f * x * (1.0f + erff(x * 0.70710678118654752f));
    float v = gl * Wd2[t];
    #pragma unroll
    for (int o = 16; o > 0; o >>= 1) v += __shfl_xor_sync(0xffffffffu, v, o);
    __shared__ float ws[8];
    if ((t & 31) == 0) ws[t >> 5] = v;
    __syncthreads();
    if (t == 0) {
        float s = 0.f;
        #pragma unroll
        for (int i = 0; i < 8; i++) s += ws[i];
        out[b] = s + bd2[0];
    }
}

// ---------------- host ----------------
static float* dev_ptr(const void* symbol)
{
    void* p = nullptr;
    cudaGetSymbolAddress(&p, symbol);
    return (float*)p;
}
static __nv_bfloat16* dev_ptr_b(const void* symbol)
{
    void* p = nullptr;
    cudaGetSymbolAddress(&p, symbol);
    return (__nv_bfloat16*)p;
}

extern "C" void kernel_launch(void* const* d_in, const int* in_sizes, int n_in,
                              void* d_out, int out_size)
{
    const float* x        = (const float*)d_in[0];
    const float* Wfc      = (const float*)d_in[3];
    const float* bfc      = (const float*)d_in[4];
    const float* cls_tok  = (const float*)d_in[5];
    const float* pos_emb  = (const float*)d_in[6];
    const float* emb1     = (const float*)d_in[7];
    const float* emb2     = (const float*)d_in[8];
    const float* Wl1      = (const float*)d_in[9];
    const float* bl1      = (const float*)d_in[10];
    const float* Wl2      = (const float*)d_in[11];
    const float* bl2      = (const float*)d_in[12];
    const float* Wqkv     = (const float*)d_in[13];
    const float* bqkv     = (const float*)d_in[14];
    const float* Wo       = (const float*)d_in[15];
    const float* bo       = (const float*)d_in[16];
    const float* W1       = (const float*)d_in[17];
    const float* b1       = (const float*)d_in[18];
    const float* W2       = (const float*)d_in[19];
    const float* b2       = (const float*)d_in[20];
    const float* ln1g     = (const float*)d_in[21];
    const float* ln1b     = (const float*)d_in[22];
    const float* ln2g     = (const float*)d_in[23];
    const float* ln2b     = (const float*)d_in[24];
    const float* Wmlp     = (const float*)d_in[25];
    const float* bmlp     = (const float*)d_in[26];
    const float* Wd1      = (const float*)d_in[27];
    const float* bd1      = (const float*)d_in[28];
    const float* Wd2      = (const float*)d_in[29];
    const float* bd2      = (const float*)d_in[30];
    float* out = (float*)d_out;

    static bool inited = false;
    static float *p_h, *p_qkv, *p_t1, *p_mpo;
    static __nv_bfloat16 *p_hh, *p_hl, *p_ah, *p_al, *p_f1h, *p_f1l;
    static __nv_bfloat16 *p_wqkvh, *p_wqkvl, *p_woh, *p_wol, *p_w1h, *p_w1l,
                         *p_w2h, *p_w2l, *p_wmh, *p_wml, *p_hoh, *p_hol;
    if (!inited) {
        cudaFuncSetAttribute(gemm_bf3_kernel,
            cudaFuncAttributeMaxDynamicSharedMemorySize, SMEM_GEMM_BYTES);
        cudaFuncSetAttribute(head_gemm_kernel,
            cudaFuncAttributeMaxDynamicSharedMemorySize, C_ * NCLS * H_ * 4);
        p_h = dev_ptr(g_h); p_qkv = dev_ptr(g_qkv); p_t1 = dev_ptr(g_t1);
        p_mpo = dev_ptr(g_mpo);
        p_hh = dev_ptr_b(g_hh); p_hl = dev_ptr_b(g_hl);
        p_ah = dev_ptr_b(g_ah); p_al = dev_ptr_b(g_al);
        p_f1h = dev_ptr_b(g_f1h); p_f1l = dev_ptr_b(g_f1l);
        p_wqkvh = dev_ptr_b(g_wqkvh); p_wqkvl = dev_ptr_b(g_wqkvl);
        p_woh = dev_ptr_b(g_woh); p_wol = dev_ptr_b(g_wol);
        p_w1h = dev_ptr_b(g_w1h); p_w1l = dev_ptr_b(g_w1l);
        p_w2h = dev_ptr_b(g_w2h); p_w2l = dev_ptr_b(g_w2l);
        p_wmh = dev_ptr_b(g_wmh); p_wml = dev_ptr_b(g_wml);
        p_hoh = dev_ptr_b(g_hoh); p_hol = dev_ptr_b(g_hol);
        inited = true;
    }

    // weight conversion (fp32 -> bf16 hi/lo)
    conv_pair_kernel<<<(LAYERS * 3 * H_ * H_) / 256, 256>>>(Wqkv, p_wqkvh, p_wqkvl, LAYERS * 3 * H_ * H_);
    conv_pair_kernel<<<(LAYERS * H_ * H_) / 256, 256>>>(Wo, p_woh, p_wol, LAYERS * H_ * H_);
    conv_pair_kernel<<<(LAYERS * 4 * H_ * H_) / 256, 256>>>(W1, p_w1h, p_w1l, LAYERS * 4 * H_ * H_);
    conv_pair_kernel<<<(LAYERS * 4 * H_ * H_) / 256, 256>>>(W2, p_w2h, p_w2l, LAYERS * 4 * H_ * H_);
    conv_pair_kernel<<<((LAYERS - 1) * H_ * 3 * H_) / 256, 256>>>(Wmlp, p_wmh, p_wml, (LAYERS - 1) * H_ * 3 * H_);

    graph_kernel<<<1, 256>>>(emb1, emb2, Wl1, bl1, Wl2, bl2);
    embed_kernel<<<ROWS, 256>>>(x, Wfc, bfc, cls_tok, pos_emb);

    const int MP_THREADS = BS * C_ * NCLS * H_;   // 1,048,576

    for (int l = 0; l < LAYERS; l++) {
        if (l > 0) {
            mp_fused_kernel<<<BS * NCLS, 256>>>();
            gemm_bf3_kernel<<<dim3(2, 32), 256, SMEM_GEMM_BYTES>>>(
                p_hoh, p_hol,
                p_wmh + (size_t)(l - 1) * H_ * 3 * H_, p_wml + (size_t)(l - 1) * H_ * 3 * H_,
                bmlp + (size_t)(l - 1) * H_,
                p_mpo, nullptr, nullptr,
                BS * C_ * NCLS, H_, 3 * H_, 0);
            mp_scatter_kernel<<<MP_THREADS / 256, 256>>>();
        }

        // QKV projection
        gemm_bf3_kernel<<<dim3(6, ROWS / 128), 256, SMEM_GEMM_BYTES>>>(
            p_hh, p_hl,
            p_wqkvh + (size_t)l * 3 * H_ * H_, p_wqkvl + (size_t)l * 3 * H_ * H_,
            bqkv + (size_t)l * 3 * H_,
            p_qkv, nullptr, nullptr, ROWS, 3 * H_, H_, 0);

        attn_kernel<<<BP * NH_, 128>>>(p_qkv);

        // output projection -> g_t1
        gemm_bf3_kernel<<<dim3(2, ROWS / 128), 256, SMEM_GEMM_BYTES>>>(
            p_ah, p_al,
            p_woh + (size_t)l * H_ * H_, p_wol + (size_t)l * H_ * H_,
            bo + (size_t)l * H_,
            p_t1, nullptr, nullptr, ROWS, H_, H_, 0);

        add_ln_kernel<<<ROWS, 256>>>(p_t1, ln1g + l * H_, ln1b + l * H_);

        // FFN
        gemm_bf3_kernel<<<dim3(8, ROWS / 128), 256, SMEM_GEMM_BYTES>>>(
            p_hh, p_hl,
            p_w1h + (size_t)l * 4 * H_ * H_, p_w1l + (size_t)l * 4 * H_ * H_,
            b1 + (size_t)l * 4 * H_,
            nullptr, p_f1h, p_f1l, ROWS, 4 * H_, H_, 1);

        gemm_bf3_kernel<<<dim3(2, ROWS / 128), 256, SMEM_GEMM_BYTES>>>(
            p_f1h, p_f1l,
            p_w2h + (size_t)l * 4 * H_ * H_, p_w2l + (size_t)l * 4 * H_ * H_,
            b2 + (size_t)l * H_,
            p_t1, nullptr, nullptr, ROWS, H_, 4 * H_, 0);

        add_ln_kernel<<<ROWS, 256>>>(p_t1, ln2g + l * H_, ln2b + l * H_);
    }

    tanh_gather_kernel<<<MP_THREADS / 256, 256>>>();
    head_gemm_kernel<<<BS, 512, C_ * NCLS * H_ * 4>>>(Wd1, bd1);
    head_kernel<<<BS, 256>>>(Wd2, bd2, out);
}

// round 11
// speedup vs baseline: 1.2585x; 1.0034x over previous
#include <cuda_runtime.h>
#include <cuda_bf16.h>
#include <cuda_fp16.h>
#include <math.h>
#include <stdint.h>

// ---------------- model constants ----------------
#define BS    64
#define T_    96
#define C_    16
#define IN_   16
#define H_    256
#define NH_   8
#define DH_   32
#define NCLS  4
#define L_    100          // T + NCLS
#define LAYERS 4
#define BP    (BS * C_)    // 1024 sequences
#define ROWS  (BP * L_)    // 102400 token rows
#define EPS_  1e-5f

// ================= low-level helpers =================
__device__ __forceinline__ uint32_t smem_u32(const void* p) {
    uint32_t a;
    asm("{ .reg .u64 t; cvta.to.shared.u64 t, %1; cvt.u32.u64 %0, t; }"
        : "=r"(a) : "l"(p));
    return a;
}
__device__ __forceinline__ void cp16(uint32_t dst, const void* src) {
    asm volatile("cp.async.cg.shared.global [%0], [%1], 16;" :: "r"(dst), "l"(src) : "memory");
}
__device__ __forceinline__ void ldsm4(uint32_t* r, uint32_t addr) {
    asm volatile("ldmatrix.sync.aligned.m8n8.x4.shared.b16 {%0,%1,%2,%3}, [%4];"
        : "=r"(r[0]), "=r"(r[1]), "=r"(r[2]), "=r"(r[3]) : "r"(addr));
}
__device__ __forceinline__ void ldsm2(uint32_t* r, uint32_t addr) {
    asm volatile("ldmatrix.sync.aligned.m8n8.x2.shared.b16 {%0,%1}, [%2];"
        : "=r"(r[0]), "=r"(r[1]) : "r"(addr));
}
__device__ __forceinline__ void mma16816(float* d, const uint32_t* a, const uint32_t* b) {
    asm volatile("mma.sync.aligned.m16n8k16.row.col.f32.bf16.bf16.f32 "
        "{%0,%1,%2,%3}, {%4,%5,%6,%7}, {%8,%9}, {%0,%1,%2,%3};"
        : "+f"(d[0]), "+f"(d[1]), "+f"(d[2]), "+f"(d[3])
        : "r"(a[0]), "r"(a[1]), "r"(a[2]), "r"(a[3]), "r"(b[0]), "r"(b[1]));
}

// ---------------- bf16 split helper ----------------
__device__ __forceinline__ void split_bf16(float v, __nv_bfloat16& hi, __nv_bfloat16& lo) {
    hi = __float2bfloat16(v);
    lo = __float2bfloat16(v - __bfloat162float(hi));
}

// ---------------- scratch (device globals) -------------
__device__ __align__(256) float         g_h  [(size_t)ROWS * H_];
__device__ __align__(256) __nv_bfloat16 g_hh [(size_t)ROWS * H_];
__device__ __align__(256) __nv_bfloat16 g_hl [(size_t)ROWS * H_];
__device__ __align__(256) __half        g_qkv[(size_t)ROWS * 3 * H_];   // fp16 now
__device__ __align__(256) __nv_bfloat16 g_ah [(size_t)ROWS * H_];
__device__ __align__(256) __nv_bfloat16 g_al [(size_t)ROWS * H_];
__device__ __align__(256) float         g_t1 [(size_t)ROWS * H_];
__device__ __align__(256) __nv_bfloat16 g_f1h[(size_t)ROWS * 4 * H_];
__device__ __align__(256) __nv_bfloat16 g_f1l[(size_t)ROWS * 4 * H_];
// weights (bf16 pairs)
__device__ __align__(256) __nv_bfloat16 g_wqkvh[LAYERS * 3 * H_ * H_], g_wqkvl[LAYERS * 3 * H_ * H_];
__device__ __align__(256) __nv_bfloat16 g_woh  [LAYERS * H_ * H_],     g_wol  [LAYERS * H_ * H_];
__device__ __align__(256) __nv_bfloat16 g_w1h  [LAYERS * 4 * H_ * H_], g_w1l  [LAYERS * 4 * H_ * H_];
__device__ __align__(256) __nv_bfloat16 g_w2h  [LAYERS * 4 * H_ * H_], g_w2l  [LAYERS * 4 * H_ * H_];
__device__ __align__(256) __nv_bfloat16 g_wmh  [(LAYERS-1) * H_ * 3 * H_], g_wml[(LAYERS-1) * H_ * 3 * H_];
// graph / mixprop
__device__ float g_m1 [C_ * H_];
__device__ float g_m2 [C_ * H_];
__device__ float g_adj[C_ * C_];
__device__ __align__(256) __nv_bfloat16 g_hoh[(size_t)BS * C_ * NCLS * 3 * H_];
__device__ __align__(256) __nv_bfloat16 g_hol[(size_t)BS * C_ * NCLS * 3 * H_];
__device__ __align__(256) float g_mpo[(size_t)BS * C_ * NCLS * H_];
__device__ __align__(256) float g_z  [(size_t)BS * C_ * NCLS * H_];
__device__ float g_d1 [BS * H_];

// ================= HMMA GEMM (bf16x3, mma.sync, 2-stage) =================
// C[M,N] = A[M,K] @ B[N,K]^T + bias.
// mode 0: fp32 out; mode 1: relu + bf16 pair; mode 2: fp16 out (Cf cast).
#define ASTR    40                        // bf16 row pitch (80B) — conflict-free
#define TILE_B  (128 * ASTR * 2)          // 10240 bytes per buffer
#define STAGE_B (4 * TILE_B)              // Ah, Al, Bh, Bl
#define SMEM_GEMM_BYTES (2 * STAGE_B)     // 81920 -> 2 CTAs/SM
#define OFF_AH  0
#define OFF_AL  TILE_B
#define OFF_BH  (2 * TILE_B)
#define OFF_BL  (3 * TILE_B)

__global__ __launch_bounds__(256) void gemm_bf3_kernel(
    const __nv_bfloat16* __restrict__ Ah, const __nv_bfloat16* __restrict__ Al,
    const __nv_bfloat16* __restrict__ Bh, const __nv_bfloat16* __restrict__ Bl,
    const float* __restrict__ bias,
    float* __restrict__ Cf, __nv_bfloat16* __restrict__ Ch, __nv_bfloat16* __restrict__ Cl,
    int M, int N, int K, int mode)
{
    extern __shared__ char smem[];
    uint32_t sb = smem_u32(smem);
    int tid = threadIdx.x;
    int lane = tid & 31;
    int w = tid >> 5;
    int wm = w >> 2;            // 0..1
    int wn = w & 3;             // 0..3
    int m0 = blockIdx.y * 128, n0 = blockIdx.x * 128;

    float acc[4][4][4];
    #pragma unroll
    for (int i = 0; i < 4; i++)
        #pragma unroll
        for (int j = 0; j < 4; j++)
            #pragma unroll
            for (int k = 0; k < 4; k++) acc[i][j][k] = 0.f;

    int nch = K >> 5;

    #define ISSUE_STAGE(cidx) do {                                               \
        int _s = (cidx) & 1; int _kc = (cidx) << 5;                              \
        uint32_t _base = sb + _s * STAGE_B;                                      \
        _Pragma("unroll")                                                        \
        for (int _i = 0; _i < 2; _i++) {                                         \
            int _id = tid + _i * 256;                                            \
            int _r = _id >> 2;                                                   \
            int _cc = (_id & 3) << 3;                                            \
            uint32_t _do = (uint32_t)(_r * (ASTR * 2) + _cc * 2);                \
            size_t _ga = (size_t)(m0 + _r) * K + _kc + _cc;                      \
            size_t _gb = (size_t)(n0 + _r) * K + _kc + _cc;                      \
            cp16(_base + OFF_AH + _do, Ah + _ga);                                \
            cp16(_base + OFF_AL + _do, Al + _ga);                                \
            cp16(_base + OFF_BH + _do, Bh + _gb);                                \
            cp16(_base + OFF_BL + _do, Bl + _gb);                                \
        }                                                                        \
        asm volatile("cp.async.commit_group;" ::: "memory");                     \
    } while (0)

    ISSUE_STAGE(0);

    for (int c = 0; c < nch; c++) {
        if (c + 1 < nch) {
            ISSUE_STAGE(c + 1);
            asm volatile("cp.async.wait_group 1;" ::: "memory");
        } else {
            asm volatile("cp.async.wait_group 0;" ::: "memory");
        }
        __syncthreads();

        uint32_t base = sb + (c & 1) * STAGE_B;
        #pragma unroll
        for (int ks = 0; ks < 2; ks++) {
            uint32_t ah[4][4], al[4][4], bh[4][2], bl[4][2];
            int arow = wm * 64 + (lane & 15);
            int akc  = ks * 16 + (lane >> 4) * 8;
            #pragma unroll
            for (int mf = 0; mf < 4; mf++) {
                uint32_t off = (uint32_t)(((arow + mf * 16) * ASTR + akc) * 2);
                ldsm4(ah[mf], base + OFF_AH + off);
                ldsm4(al[mf], base + OFF_AL + off);
            }
            int brow = wn * 32 + (lane & 7);
            int bkc  = ks * 16 + (((lane & 15) >> 3)) * 8;
            #pragma unroll
            for (int nf = 0; nf < 4; nf++) {
                uint32_t off = (uint32_t)(((brow + nf * 8) * ASTR + bkc) * 2);
                ldsm2(bh[nf], base + OFF_BH + off);
                ldsm2(bl[nf], base + OFF_BL + off);
            }
            #pragma unroll
            for (int mf = 0; mf < 4; mf++)
                #pragma unroll
                for (int nf = 0; nf < 4; nf++) {
                    mma16816(acc[mf][nf], ah[mf], bh[nf]);
                    mma16816(acc[mf][nf], ah[mf], bl[nf]);
                    mma16816(acc[mf][nf], al[mf], bh[nf]);
                }
        }
        __syncthreads();
    }

    // ---- epilogue ----
    int rbase = m0 + wm * 64 + (lane >> 2);
    int cbase = n0 + wn * 32 + (lane & 3) * 2;
    #pragma unroll
    for (int mf = 0; mf < 4; mf++) {
        #pragma unroll
        for (int nf = 0; nf < 4; nf++) {
            int r = rbase + mf * 16;
            int cc = cbase + nf * 8;
            float b0 = bias[cc], b1 = bias[cc + 1];
            float v0 = acc[mf][nf][0] + b0, v1 = acc[mf][nf][1] + b1;
            float v2 = acc[mf][nf][2] + b0, v3 = acc[mf][nf][3] + b1;
            if (mode == 0) {
                *(float2*)(Cf + (size_t)r * N + cc)       = make_float2(v0, v1);
                *(float2*)(Cf + (size_t)(r + 8) * N + cc) = make_float2(v2, v3);
            } else if (mode == 2) {
                __half* Hc = (__half*)Cf;
                *(__half2*)(Hc + (size_t)r * N + cc)       = __floats2half2_rn(v0, v1);
                *(__half2*)(Hc + (size_t)(r + 8) * N + cc) = __floats2half2_rn(v2, v3);
            } else {
                v0 = fmaxf(v0, 0.f); v1 = fmaxf(v1, 0.f);
                v2 = fmaxf(v2, 0.f); v3 = fmaxf(v3, 0.f);
                __nv_bfloat16 h0, l0, h1, l1, h2, l2, h3, l3;
                split_bf16(v0, h0, l0); split_bf16(v1, h1, l1);
                split_bf16(v2, h2, l2); split_bf16(v3, h3, l3);
                __nv_bfloat162 hh0; hh0.x = h0; hh0.y = h1;
                __nv_bfloat162 ll0; ll0.x = l0; ll0.y = l1;
                __nv_bfloat162 hh1; hh1.x = h2; hh1.y = h3;
                __nv_bfloat162 ll1; ll1.x = l2; ll1.y = l3;
                *(__nv_bfloat162*)(Ch + (size_t)r * N + cc)       = hh0;
                *(__nv_bfloat162*)(Cl + (size_t)r * N + cc)       = ll0;
                *(__nv_bfloat162*)(Ch + (size_t)(r + 8) * N + cc) = hh1;
                *(__nv_bfloat162*)(Cl + (size_t)(r + 8) * N + cc) = ll1;
            }
        }
    }
}

// ================= misc kernels =================
// single merged weight conversion (float4-vectorized, 5 segments)
#define NWQKV (LAYERS * 3 * H_ * H_)      // 786432
#define NWO   (LAYERS * H_ * H_)          // 262144
#define NW1   (LAYERS * 4 * H_ * H_)      // 1048576
#define NW2   (LAYERS * 4 * H_ * H_)      // 1048576
#define NWM   ((LAYERS - 1) * H_ * 3 * H_) // 589824
#define NCONV ((NWQKV + NWO + NW1 + NW2 + NWM) / 4)  // float4 count: 933888

__global__ __launch_bounds__(256) void conv_all_kernel(
    const float* __restrict__ Wqkv, const float* __restrict__ Wo,
    const float* __restrict__ W1,   const float* __restrict__ W2,
    const float* __restrict__ Wm)
{
    int i4 = blockIdx.x * 256 + threadIdx.x;
    if (i4 >= NCONV) return;
    int i = i4 * 4;
    const float* src; __nv_bfloat16 *hi, *lo; int off;
    if (i < NWQKV) { src = Wqkv; hi = g_wqkvh; lo = g_wqkvl; off = i; }
    else if (i < NWQKV + NWO) { src = Wo; hi = g_woh; lo = g_wol; off = i - NWQKV; }
    else if (i < NWQKV + NWO + NW1) { src = W1; hi = g_w1h; lo = g_w1l; off = i - NWQKV - NWO; }
    else if (i < NWQKV + NWO + NW1 + NW2) { src = W2; hi = g_w2h; lo = g_w2l; off = i - NWQKV - NWO - NW1; }
    else { src = Wm; hi = g_wmh; lo = g_wml; off = i - NWQKV - NWO - NW1 - NW2; }
    float4 v = *(const float4*)(src + off);
    __nv_bfloat16 h0, l0, h1, l1, h2, l2, h3, l3;
    split_bf16(v.x, h0, l0); split_bf16(v.y, h1, l1);
    split_bf16(v.z, h2, l2); split_bf16(v.w, h3, l3);
    __nv_bfloat162 p0; p0.x = h0; p0.y = h1;
    __nv_bfloat162 p1; p1.x = h2; p1.y = h3;
    __nv_bfloat162 q0; q0.x = l0; q0.y = l1;
    __nv_bfloat162 q1; q1.x = l2; q1.y = l3;
    *(__nv_bfloat162*)(hi + off)     = p0;
    *(__nv_bfloat162*)(hi + off + 2) = p1;
    *(__nv_bfloat162*)(lo + off)     = q0;
    *(__nv_bfloat162*)(lo + off + 2) = q1;
}

__global__ __launch_bounds__(256) void embed_kernel(
    const float* __restrict__ x, const float* __restrict__ Wfc,
    const float* __restrict__ bfc, const float* __restrict__ cls,
    const float* __restrict__ pos)
{
    int row = blockIdx.x;
    int l  = row % L_;
    int bc = row / L_;
    int c  = bc % C_;
    int b  = bc / C_;
    int t  = threadIdx.x;

    __shared__ float xs[IN_];
    float val;
    if (l < T_) {
        if (t < IN_) xs[t] = x[(((size_t)b * T_ + l) * C_ + c) * IN_ + t];
        __syncthreads();
        float s = bfc[t];
        #pragma unroll
        for (int i = 0; i < IN_; i++) s += xs[i] * Wfc[t * IN_ + i];
        val = s;
    } else {
        val = cls[((l - T_) * C_ + c) * H_ + t];
    }
    val += pos[((size_t)l * C_ + c) * H_ + t];
    size_t o = (size_t)row * H_ + t;
    g_h[o] = val;
    __nv_bfloat16 h, lo_;
    split_bf16(val, h, lo_);
    g_hh[o] = h; g_hl[o] = lo_;
}

__global__ __launch_bounds__(256) void graph_kernel(
    const float* __restrict__ emb1, const float* __restrict__ emb2,
    const float* __restrict__ Wl1, const float* __restrict__ bl1,
    const float* __restrict__ Wl2, const float* __restrict__ bl2)
{
    int t = threadIdx.x;
    for (int i = 0; i < C_; i++) {
        float s1 = bl1[t], s2 = bl2[t];
        for (int k = 0; k < H_; k++) {
            s1 += emb1[i * H_ + k] * Wl1[t * H_ + k];
            s2 += emb2[i * H_ + k] * Wl2[t * H_ + k];
        }
        g_m1[i * H_ + t] = tanhf(s1);
        g_m2[i * H_ + t] = tanhf(s2);
    }
    __syncthreads();

    __shared__ float adj[C_][C_];
    __shared__ float rsum[C_];
    int v = t >> 4, w = t & 15;
    float s = 0.f;
    for (int j = 0; j < H_; j++)
        s += g_m1[v * H_ + j] * g_m2[w * H_ + j]
           - g_m2[v * H_ + j] * g_m1[w * H_ + j];
    float gv = fmaxf(tanhf(s), 0.f);
    if (v == w) gv += 1.0f;
    adj[v][w] = gv;
    __syncthreads();
    if (t < C_) {
        float r = 0.f;
        for (int k = 0; k < C_; k++) r += adj[t][k];
        rsum[t] = r;
    }
    __syncthreads();
    g_adj[t] = adj[v][w] / rsum[v];
}

// ================= attention (online softmax, fp16 qkv in, float4 SMEM) ====
__global__ __launch_bounds__(128) void attn_kernel(const __half* __restrict__ qkv)
{
    int bh = blockIdx.x;
    int b = bh >> 3;
    int h = bh & 7;
    __shared__ float4 Ks[L_][8];
    __shared__ float4 Vs[L_][8];
    const __half* base = qkv + (size_t)b * L_ * (3 * H_) + h * DH_;
    for (int idx = threadIdx.x; idx < L_ * 8; idx += 128) {
        int l = idx >> 3, k4 = idx & 7;
        const __half2* kp = (const __half2*)(base + (size_t)l * (3 * H_) + H_     + k4 * 4);
        const __half2* vp = (const __half2*)(base + (size_t)l * (3 * H_) + 2 * H_ + k4 * 4);
        float2 k0 = __half22float2(kp[0]), k1 = __half22float2(kp[1]);
        float2 vv0 = __half22float2(vp[0]), vv1 = __half22float2(vp[1]);
        Ks[l][k4] = make_float4(k0.x, k0.y, k1.x, k1.y);
        Vs[l][k4] = make_float4(vv0.x, vv0.y, vv1.x, vv1.y);
    }
    __syncthreads();

    int i = threadIdx.x;
    if (i < L_) {
        float4 q[8];
        #pragma unroll
        for (int k4 = 0; k4 < 8; k4++) {
            const __half2* qp = (const __half2*)(base + (size_t)i * (3 * H_) + k4 * 4);
            float2 q0 = __half22float2(qp[0]), q1 = __half22float2(qp[1]);
            q[k4] = make_float4(q0.x, q0.y, q1.x, q1.y);
        }

        float m = -1e30f, lsum = 0.f;
        float4 acc[8];
        #pragma unroll
        for (int k4 = 0; k4 < 8; k4++) acc[k4] = make_float4(0.f, 0.f, 0.f, 0.f);

        int jmax = (i >= T_) ? L_ : (i + 1);
        for (int j = 0; j < jmax; j++) {
            float a0 = 0.f, a1 = 0.f, a2 = 0.f, a3 = 0.f;
            #pragma unroll
            for (int k4 = 0; k4 < 8; k4++) {
                float4 kv = Ks[j][k4];
                a0 += q[k4].x * kv.x;
                a1 += q[k4].y * kv.y;
                a2 += q[k4].z * kv.z;
                a3 += q[k4].w * kv.w;
            }
            float s = ((a0 + a1) + (a2 + a3)) * 0.17677669529663687f;
            if (s <= m) {
                float p = __expf(s - m);
                lsum += p;
                #pragma unroll
                for (int k4 = 0; k4 < 8; k4++) {
                    float4 vv = Vs[j][k4];
                    acc[k4].x += p * vv.x;
                    acc[k4].y += p * vv.y;
                    acc[k4].z += p * vv.z;
                    acc[k4].w += p * vv.w;
                }
            } else {
                float sc = __expf(m - s);
                lsum = lsum * sc + 1.f;
                #pragma unroll
                for (int k4 = 0; k4 < 8; k4++) {
                    float4 vv = Vs[j][k4];
                    acc[k4].x = acc[k4].x * sc + vv.x;
                    acc[k4].y = acc[k4].y * sc + vv.y;
                    acc[k4].z = acc[k4].z * sc + vv.z;
                    acc[k4].w = acc[k4].w * sc + vv.w;
                }
                m = s;
            }
        }
        float inv = 1.f / lsum;
        size_t o = ((size_t)b * L_ + i) * H_ + h * DH_;
        #pragma unroll
        for (int k4 = 0; k4 < 8; k4++) {
            float v0 = acc[k4].x * inv, v1 = acc[k4].y * inv;
            float v2 = acc[k4].z * inv, v3 = acc[k4].w * inv;
            __nv_bfloat16 h0, l0, h1, l1, h2, l2, h3, l3;
            split_bf16(v0, h0, l0); split_bf16(v1, h1, l1);
            split_bf16(v2, h2, l2); split_bf16(v3, h3, l3);
            __nv_bfloat162 hh0; hh0.x = h0; hh0.y = h1;
            __nv_bfloat162 ll0; ll0.x = l0; ll0.y = l1;
            __nv_bfloat162 hh1; hh1.x = h2; hh1.y = h3;
            __nv_bfloat162 ll1; ll1.x = l2; ll1.y = l3;
            *(__nv_bfloat162*)(g_ah + o + k4 * 4)     = hh0;
            *(__nv_bfloat162*)(g_al + o + k4 * 4)     = ll0;
            *(__nv_bfloat162*)(g_ah + o + k4 * 4 + 2) = hh1;
            *(__nv_bfloat162*)(g_al + o + k4 * 4 + 2) = ll1;
        }
    }
}

// fused residual-add + LayerNorm; writes fp32 h and bf16 pair
__global__ __launch_bounds__(256) void add_ln_kernel(
    const float* __restrict__ xin,
    const float* __restrict__ g, const float* __restrict__ bt)
{
    int row = blockIdx.x, t = threadIdx.x;
    size_t base = (size_t)row * H_;
    float v = g_h[base + t] + xin[base + t];

    __shared__ float ws[8];
    float s = v;
    #pragma unroll
    for (int o = 16; o > 0; o >>= 1) s += __shfl_xor_sync(0xffffffffu, s, o);
    if ((t & 31) == 0) ws[t >> 5] = s;
    __syncthreads();
    float tot = 0.f;
    #pragma unroll
    for (int i = 0; i < 8; i++) tot += ws[i];
    float mean = tot * (1.0f / H_);
    float d = v - mean;
    __syncthreads();

    float q = d * d;
    #pragma unroll
    for (int o = 16; o > 0; o >>= 1) q += __shfl_xor_sync(0xffffffffu, q, o);
    if ((t & 31) == 0) ws[t >> 5] = q;
    __syncthreads();
    float qt = 0.f;
    #pragma unroll
    for (int i = 0; i < 8; i++) qt += ws[i];
    float var = qt * (1.0f / H_);

    float out = d * rsqrtf(var + EPS_) * g[t] + bt[t];
    g_h[base + t] = out;
    __nv_bfloat16 hh, ll;
    split_bf16(out, hh, ll);
    g_hh[base + t] = hh; g_hl[base + t] = ll;
}

// ---------------- fused mixprop (gather + 2 prop depths + bf16 pair out) ---
__global__ __launch_bounds__(256) void mp_fused_kernel()
{
    __shared__ float s0[C_ * H_];
    __shared__ float s1[C_ * H_];
    __shared__ float adjs[C_ * C_];

    int n = blockIdx.x >> 2;
    int l = blockIdx.x & 3;
    int t = threadIdx.x;
    adjs[t] = g_adj[t];

    #pragma unroll
    for (int w = 0; w < C_; w++) {
        float v = g_h[(((size_t)(n * C_ + w)) * L_ + T_ + l) * H_ + t];
        s0[w * H_ + t] = v;
        size_t r = (size_t)((n * C_ + w) * NCLS + l) * (3 * H_);
        __nv_bfloat16 hh, ll;
        split_bf16(v, hh, ll);
        g_hoh[r + t] = hh; g_hol[r + t] = ll;
    }
    __syncthreads();

    #pragma unroll
    for (int v = 0; v < C_; v++) {
        float s = 0.f;
        #pragma unroll
        for (int w = 0; w < C_; w++)
            s += adjs[v * C_ + w] * s0[w * H_ + t];
        s1[v * H_ + t] = s;
        size_t r = (size_t)((n * C_ + v) * NCLS + l) * (3 * H_) + H_;
        __nv_bfloat16 hh, ll;
        split_bf16(s, hh, ll);
        g_hoh[r + t] = hh; g_hol[r + t] = ll;
    }
    __syncthreads();

    #pragma unroll
    for (int v = 0; v < C_; v++) {
        float s = 0.f;
        #pragma unroll
        for (int w = 0; w < C_; w++)
            s += adjs[v * C_ + w] * s1[w * H_ + t];
        size_t r = (size_t)((n * C_ + v) * NCLS + l) * (3 * H_) + 2 * H_;
        __nv_bfloat16 hh, ll;
        split_bf16(s, hh, ll);
        g_hoh[r + t] = hh; g_hol[r + t] = ll;
    }
}

__global__ __launch_bounds__(256) void mp_scatter_kernel()
{
    int idx = blockIdx.x * 256 + threadIdx.x;
    int o  = idx & 255;
    int r  = idx >> 8;
    int l  = r & 3;
    int nw = r >> 2;
    float v = g_mpo[(size_t)r * H_ + o];
    size_t dst = ((size_t)nw * L_ + T_ + l) * H_ + o;
    g_h[dst] = v;
    __nv_bfloat16 hh, ll;
    split_bf16(v, hh, ll);
    g_hh[dst] = hh; g_hl[dst] = ll;
}

// ---------------- head ----------------
__global__ __launch_bounds__(256) void tanh_gather_kernel()
{
    int idx = blockIdx.x * 256 + threadIdx.x;
    int hd = idx & 255;
    int r  = idx >> 8;
    int n  = r & 3;
    int c  = (r >> 2) & 15;
    int b  = r >> 6;
    g_z[idx] = tanhf(g_h[(((size_t)(b * C_ + c)) * L_ + T_ + n) * H_ + hd]);
}

__global__ __launch_bounds__(512) void head_gemm_kernel(
    const float* __restrict__ Wd1, const float* __restrict__ bd1)
{
    extern __shared__ float zs[];
    int b = blockIdx.x;
    int tid = threadIdx.x;
    for (int i = tid; i < C_ * NCLS * H_; i += 512)
        zs[i] = g_z[(size_t)b * (C_ * NCLS * H_) + i];
    __syncthreads();
    int wid = tid >> 5, lane = tid & 31;
    for (int o = wid; o < H_; o += 16) {
        const float* w = Wd1 + (size_t)o * (C_ * NCLS * H_);
        float s = 0.f;
        for (int k = lane; k < C_ * NCLS * H_; k += 32)
            s += zs[k] * w[k];
        #pragma unroll
        for (int off = 16; off > 0; off >>= 1)
            s += __shfl_xor_sync(0xffffffffu, s, off);
        if (lane == 0) g_d1[b * H_ + o] = s + bd1[o];
    }
}

__global__ __launch_bounds__(256) void head_kernel(
    const float* __restrict__ Wd2, const float* __restrict__ bd2,
    float* __restrict__ out)
{
    int b = blockIdx.x, t = threadIdx.x;
    float x = g_d1[b * H_ + t];
    float gl = 0.5f * x * (1.0f + erff(x * 0.70710678118654752f));
    float v = gl * Wd2[t];
    #pragma unroll
    for (int o = 16; o > 0; o >>= 1) v += __shfl_xor_sync(0xffffffffu, v, o);
    __shared__ float ws[8];
    if ((t & 31) == 0) ws[t >> 5] = v;
    __syncthreads();
    if (t == 0) {
        float s = 0.f;
        #pragma unroll
        for (int i = 0; i < 8; i++) s += ws[i];
        out[b] = s + bd2[0];
    }
}

// ---------------- host ----------------
static float* dev_ptr(const void* symbol)
{
    void* p = nullptr;
    cudaGetSymbolAddress(&p, symbol);
    return (float*)p;
}
static __nv_bfloat16* dev_ptr_b(const void* symbol)
{
    void* p = nullptr;
    cudaGetSymbolAddress(&p, symbol);
    return (__nv_bfloat16*)p;
}

extern "C" void kernel_launch(void* const* d_in, const int* in_sizes, int n_in,
                              void* d_out, int out_size)
{
    const float* x        = (const float*)d_in[0];
    const float* Wfc      = (const float*)d_in[3];
    const float* bfc      = (const float*)d_in[4];
    const float* cls_tok  = (const float*)d_in[5];
    const float* pos_emb  = (const float*)d_in[6];
    const float* emb1     = (const float*)d_in[7];
    const float* emb2     = (const float*)d_in[8];
    const float* Wl1      = (const float*)d_in[9];
    const float* bl1      = (const float*)d_in[10];
    const float* Wl2      = (const float*)d_in[11];
    const float* bl2      = (const float*)d_in[12];
    const float* Wqkv     = (const float*)d_in[13];
    const float* bqkv     = (const float*)d_in[14];
    const float* Wo       = (const float*)d_in[15];
    const float* bo       = (const float*)d_in[16];
    const float* W1       = (const float*)d_in[17];
    const float* b1       = (const float*)d_in[18];
    const float* W2       = (const float*)d_in[19];
    const float* b2       = (const float*)d_in[20];
    const float* ln1g     = (const float*)d_in[21];
    const float* ln1b     = (const float*)d_in[22];
    const float* ln2g     = (const float*)d_in[23];
    const float* ln2b     = (const float*)d_in[24];
    const float* Wmlp     = (const float*)d_in[25];
    const float* bmlp     = (const float*)d_in[26];
    const float* Wd1      = (const float*)d_in[27];
    const float* bd1      = (const float*)d_in[28];
    const float* Wd2      = (const float*)d_in[29];
    const float* bd2      = (const float*)d_in[30];
    float* out = (float*)d_out;

    static bool inited = false;
    static float *p_h, *p_t1, *p_mpo;
    static __half *p_qkv;
    static __nv_bfloat16 *p_hh, *p_hl, *p_ah, *p_al, *p_f1h, *p_f1l;
    static __nv_bfloat16 *p_wqkvh, *p_wqkvl, *p_woh, *p_wol, *p_w1h, *p_w1l,
                         *p_w2h, *p_w2l, *p_wmh, *p_wml, *p_hoh, *p_hol;
    if (!inited) {
        cudaFuncSetAttribute(gemm_bf3_kernel,
            cudaFuncAttributeMaxDynamicSharedMemorySize, SMEM_GEMM_BYTES);
        cudaFuncSetAttribute(head_gemm_kernel,
            cudaFuncAttributeMaxDynamicSharedMemorySize, C_ * NCLS * H_ * 4);
        p_h = dev_ptr(g_h); p_t1 = dev_ptr(g_t1); p_mpo = dev_ptr(g_mpo);
        p_qkv = (__half*)dev_ptr(g_qkv);
        p_hh = dev_ptr_b(g_hh); p_hl = dev_ptr_b(g_hl);
        p_ah = dev_ptr_b(g_ah); p_al = dev_ptr_b(g_al);
        p_f1h = dev_ptr_b(g_f1h); p_f1l = dev_ptr_b(g_f1l);
        p_wqkvh = dev_ptr_b(g_wqkvh); p_wqkvl = dev_ptr_b(g_wqkvl);
        p_woh = dev_ptr_b(g_woh); p_wol = dev_ptr_b(g_wol);
        p_w1h = dev_ptr_b(g_w1h); p_w1l = dev_ptr_b(g_w1l);
        p_w2h = dev_ptr_b(g_w2h); p_w2l = dev_ptr_b(g_w2l);
        p_wmh = dev_ptr_b(g_wmh); p_wml = dev_ptr_b(g_wml);
        p_hoh = dev_ptr_b(g_hoh); p_hol = dev_ptr_b(g_hol);
        inited = true;
    }

    // launch 0: merged weight conversion
    conv_all_kernel<<<(NCONV + 255) / 256, 256>>>(Wqkv, Wo, W1, W2, Wmlp);
    // launch 1-2
    graph_kernel<<<1, 256>>>(emb1, emb2, Wl1, bl1, Wl2, bl2);
    embed_kernel<<<ROWS, 256>>>(x, Wfc, bfc, cls_tok, pos_emb);

    const int MP_THREADS = BS * C_ * NCLS * H_;   // 1,048,576

    for (int l = 0; l < LAYERS; l++) {
        if (l > 0) {
            mp_fused_kernel<<<BS * NCLS, 256>>>();
            gemm_bf3_kernel<<<dim3(2, 32), 256, SMEM_GEMM_BYTES>>>(
                p_hoh, p_hol,
                p_wmh + (size_t)(l - 1) * H_ * 3 * H_, p_wml + (size_t)(l - 1) * H_ * 3 * H_,
                bmlp + (size_t)(l - 1) * H_,
                p_mpo, nullptr, nullptr,
                BS * C_ * NCLS, H_, 3 * H_, 0);
            mp_scatter_kernel<<<MP_THREADS / 256, 256>>>();
        }

        // QKV projection -> fp16 (launch 3 on first layer)
        gemm_bf3_kernel<<<dim3(6, ROWS / 128), 256, SMEM_GEMM_BYTES>>>(
            p_hh, p_hl,
            p_wqkvh + (size_t)l * 3 * H_ * H_, p_wqkvl + (size_t)l * 3 * H_ * H_,
            bqkv + (size_t)l * 3 * H_,
            (float*)p_qkv, nullptr, nullptr, ROWS, 3 * H_, H_, 2);

        // launch 4 (layer 0)
        attn_kernel<<<BP * NH_, 128>>>(p_qkv);

        // output projection -> g_t1  (launch 5 on layer 0 -> ncu captures this)
        gemm_bf3_kernel<<<dim3(2, ROWS / 128), 256, SMEM_GEMM_BYTES>>>(
            p_ah, p_al,
            p_woh + (size_t)l * H_ * H_, p_wol + (size_t)l * H_ * H_,
            bo + (size_t)l * H_,
            p_t1, nullptr, nullptr, ROWS, H_, H_, 0);

        add_ln_kernel<<<ROWS, 256>>>(p_t1, ln1g + l * H_, ln1b + l * H_);

        // FFN
        gemm_bf3_kernel<<<dim3(8, ROWS / 128), 256, SMEM_GEMM_BYTES>>>(
            p_hh, p_hl,
            p_w1h + (size_t)l * 4 * H_ * H_, p_w1l + (size_t)l * 4 * H_ * H_,
            b1 + (size_t)l * 4 * H_,
            nullptr, p_f1h, p_f1l, ROWS, 4 * H_, H_, 1);

        gemm_bf3_kernel<<<dim3(2, ROWS / 128), 256, SMEM_GEMM_BYTES>>>(
            p_f1h, p_f1l,
            p_w2h + (size_t)l * 4 * H_ * H_, p_w2l + (size_t)l * 4 * H_ * H_,
            b2 + (size_t)l * H_,
            p_t1, nullptr, nullptr, ROWS, H_, 4 * H_, 0);

        add_ln_kernel<<<ROWS, 256>>>(p_t1, ln2g + l * H_, ln2b + l * H_);
    }

    tanh_gather_kernel<<<MP_THREADS / 256, 256>>>();
    head_gemm_kernel<<<BS, 512, C_ * NCLS * H_ * 4>>>(Wd1, bd1);
    head_kernel<<<BS, 256>>>(Wd2, bd2, out);
}

// round 12
// speedup vs baseline: 1.4643x; 1.1636x over previous
#include <cuda_runtime.h>
#include <cuda_bf16.h>
#include <cuda_fp16.h>
#include <math.h>
#include <stdint.h>

// ---------------- model constants ----------------
#define BS    64
#define T_    96
#define C_    16
#define IN_   16
#define H_    256
#define NH_   8
#define DH_   32
#define NCLS  4
#define L_    100          // T + NCLS
#define LAYERS 4
#define BP    (BS * C_)    // 1024 sequences
#define ROWS  (BP * L_)    // 102400 token rows
#define EPS_  1e-5f

// ================= low-level helpers =================
__device__ __forceinline__ uint32_t smem_u32(const void* p) {
    uint32_t a;
    asm("{ .reg .u64 t; cvta.to.shared.u64 t, %1; cvt.u32.u64 %0, t; }"
        : "=r"(a) : "l"(p));
    return a;
}
__device__ __forceinline__ void cp16(uint32_t dst, const void* src) {
    asm volatile("cp.async.cg.shared.global [%0], [%1], 16;" :: "r"(dst), "l"(src) : "memory");
}
__device__ __forceinline__ void ldsm4(uint32_t* r, uint32_t addr) {
    asm volatile("ldmatrix.sync.aligned.m8n8.x4.shared.b16 {%0,%1,%2,%3}, [%4];"
        : "=r"(r[0]), "=r"(r[1]), "=r"(r[2]), "=r"(r[3]) : "r"(addr));
}
__device__ __forceinline__ void ldsm2(uint32_t* r, uint32_t addr) {
    asm volatile("ldmatrix.sync.aligned.m8n8.x2.shared.b16 {%0,%1}, [%2];"
        : "=r"(r[0]), "=r"(r[1]) : "r"(addr));
}
// fp16 MMA, fp32 accumulate
__device__ __forceinline__ void mma16816h(float* d, const uint32_t* a, const uint32_t* b) {
    asm volatile("mma.sync.aligned.m16n8k16.row.col.f32.f16.f16.f32 "
        "{%0,%1,%2,%3}, {%4,%5,%6,%7}, {%8,%9}, {%0,%1,%2,%3};"
        : "+f"(d[0]), "+f"(d[1]), "+f"(d[2]), "+f"(d[3])
        : "r"(a[0]), "r"(a[1]), "r"(a[2]), "r"(a[3]), "r"(b[0]), "r"(b[1]));
}

// ---------------- fp16 split helper ----------------
__device__ __forceinline__ void split_fp16(float v, __half& hi, __half& lo) {
    hi = __float2half_rn(v);
    lo = __float2half_rn(v - __half2float(hi));
}

// ---------------- scratch (device globals) -------------
__device__ __align__(256) float  g_h  [(size_t)ROWS * H_];
__device__ __align__(256) __half g_hh [(size_t)ROWS * H_];          // A: encoder input
__device__ __align__(256) __half g_qkv[(size_t)ROWS * 3 * H_];
__device__ __align__(256) __half g_a  [(size_t)ROWS * H_];          // A: attention out
__device__ __align__(256) float  g_t1 [(size_t)ROWS * H_];
__device__ __align__(256) __half g_f1 [(size_t)ROWS * 4 * H_];      // A: relu out
// weights (fp16 pairs)
__device__ __align__(256) __half g_wqkvh[LAYERS * 3 * H_ * H_], g_wqkvl[LAYERS * 3 * H_ * H_];
__device__ __align__(256) __half g_woh  [LAYERS * H_ * H_],     g_wol  [LAYERS * H_ * H_];
__device__ __align__(256) __half g_w1h  [LAYERS * 4 * H_ * H_], g_w1l  [LAYERS * 4 * H_ * H_];
__device__ __align__(256) __half g_w2h  [LAYERS * 4 * H_ * H_], g_w2l  [LAYERS * 4 * H_ * H_];
__device__ __align__(256) __half g_wmh  [(LAYERS-1) * H_ * 3 * H_], g_wml[(LAYERS-1) * H_ * 3 * H_];
// graph / mixprop
__device__ float g_m1 [C_ * H_];
__device__ float g_m2 [C_ * H_];
__device__ float g_adj[C_ * C_];
__device__ __align__(256) __half g_ho [(size_t)BS * C_ * NCLS * 3 * H_];   // A: mixprop concat
__device__ __align__(256) float  g_mpo[(size_t)BS * C_ * NCLS * H_];
__device__ __align__(256) float  g_z  [(size_t)BS * C_ * NCLS * H_];
__device__ float g_d1 [BS * H_];

// ================= HMMA GEMM (fp16x2: A single, B pair, 2 passes) =========
// C[M,N] = A[M,K] @ B[N,K]^T + bias.
// mode 0: fp32 out; mode 1: relu + fp16 single; mode 2: fp16 out (Cf cast).
// grid = (N/128, M/128), 256 threads. M,N %128 == 0, K %32 == 0.
#define ASTR    40                        // fp16 row pitch (80B) — conflict-free
#define TILE_B  (128 * ASTR * 2)          // 10240 bytes per tile buffer
#define STAGE_B (3 * TILE_B)              // A, Bh, Bl
#define SMEM_GEMM_BYTES (2 * STAGE_B)     // 61440 -> 2+ CTAs/SM
#define OFF_A   0
#define OFF_BH  TILE_B
#define OFF_BL  (2 * TILE_B)

__global__ __launch_bounds__(256) void gemm_h2_kernel(
    const __half* __restrict__ A,
    const __half* __restrict__ Bh, const __half* __restrict__ Bl,
    const float* __restrict__ bias,
    float* __restrict__ Cf, __half* __restrict__ Ch,
    int M, int N, int K, int mode)
{
    extern __shared__ char smem[];
    uint32_t sb = smem_u32(smem);
    int tid = threadIdx.x;
    int lane = tid & 31;
    int w = tid >> 5;
    int wm = w >> 2;            // 0..1
    int wn = w & 3;             // 0..3
    int m0 = blockIdx.y * 128, n0 = blockIdx.x * 128;

    float acc[4][4][4];
    #pragma unroll
    for (int i = 0; i < 4; i++)
        #pragma unroll
        for (int j = 0; j < 4; j++)
            #pragma unroll
            for (int k = 0; k < 4; k++) acc[i][j][k] = 0.f;

    int nch = K >> 5;

    // ---- stage loader: per tile 128 rows x 32 fp16; 2 x 16B per thread ----
    #define ISSUE_STAGE(cidx) do {                                               \
        int _s = (cidx) & 1; int _kc = (cidx) << 5;                              \
        uint32_t _base = sb + _s * STAGE_B;                                      \
        _Pragma("unroll")                                                        \
        for (int _i = 0; _i < 2; _i++) {                                         \
            int _id = tid + _i * 256;                                            \
            int _r = _id >> 2;                                                   \
            int _cc = (_id & 3) << 3;                                            \
            uint32_t _do = (uint32_t)(_r * (ASTR * 2) + _cc * 2);                \
            size_t _ga = (size_t)(m0 + _r) * K + _kc + _cc;                      \
            size_t _gb = (size_t)(n0 + _r) * K + _kc + _cc;                      \
            cp16(_base + OFF_A  + _do, A  + _ga);                                \
            cp16(_base + OFF_BH + _do, Bh + _gb);                                \
            cp16(_base + OFF_BL + _do, Bl + _gb);                                \
        }                                                                        \
        asm volatile("cp.async.commit_group;" ::: "memory");                     \
    } while (0)

    ISSUE_STAGE(0);

    for (int c = 0; c < nch; c++) {
        if (c + 1 < nch) {
            ISSUE_STAGE(c + 1);
            asm volatile("cp.async.wait_group 1;" ::: "memory");
        } else {
            asm volatile("cp.async.wait_group 0;" ::: "memory");
        }
        __syncthreads();

        uint32_t base = sb + (c & 1) * STAGE_B;
        #pragma unroll
        for (int ks = 0; ks < 2; ks++) {
            uint32_t ah[4][4], bh[4][2], bl[4][2];
            int arow = wm * 64 + (lane & 15);
            int akc  = ks * 16 + (lane >> 4) * 8;
            #pragma unroll
            for (int mf = 0; mf < 4; mf++) {
                uint32_t off = (uint32_t)(((arow + mf * 16) * ASTR + akc) * 2);
                ldsm4(ah[mf], base + OFF_A + off);
            }
            int brow = wn * 32 + (lane & 7);
            int bkc  = ks * 16 + (((lane & 15) >> 3)) * 8;
            #pragma unroll
            for (int nf = 0; nf < 4; nf++) {
                uint32_t off = (uint32_t)(((brow + nf * 8) * ASTR + bkc) * 2);
                ldsm2(bh[nf], base + OFF_BH + off);
                ldsm2(bl[nf], base + OFF_BL + off);
            }
            #pragma unroll
            for (int mf = 0; mf < 4; mf++)
                #pragma unroll
                for (int nf = 0; nf < 4; nf++) {
                    mma16816h(acc[mf][nf], ah[mf], bh[nf]);
                    mma16816h(acc[mf][nf], ah[mf], bl[nf]);
                }
        }
        __syncthreads();
    }

    // ---- epilogue ----
    int rbase = m0 + wm * 64 + (lane >> 2);
    int cbase = n0 + wn * 32 + (lane & 3) * 2;
    #pragma unroll
    for (int mf = 0; mf < 4; mf++) {
        #pragma unroll
        for (int nf = 0; nf < 4; nf++) {
            int r = rbase + mf * 16;
            int cc = cbase + nf * 8;
            float b0 = bias[cc], b1 = bias[cc + 1];
            float v0 = acc[mf][nf][0] + b0, v1 = acc[mf][nf][1] + b1;
            float v2 = acc[mf][nf][2] + b0, v3 = acc[mf][nf][3] + b1;
            if (mode == 0) {
                *(float2*)(Cf + (size_t)r * N + cc)       = make_float2(v0, v1);
                *(float2*)(Cf + (size_t)(r + 8) * N + cc) = make_float2(v2, v3);
            } else if (mode == 2) {
                __half* Hc = (__half*)Cf;
                *(__half2*)(Hc + (size_t)r * N + cc)       = __floats2half2_rn(v0, v1);
                *(__half2*)(Hc + (size_t)(r + 8) * N + cc) = __floats2half2_rn(v2, v3);
            } else {
                v0 = fmaxf(v0, 0.f); v1 = fmaxf(v1, 0.f);
                v2 = fmaxf(v2, 0.f); v3 = fmaxf(v3, 0.f);
                *(__half2*)(Ch + (size_t)r * N + cc)       = __floats2half2_rn(v0, v1);
                *(__half2*)(Ch + (size_t)(r + 8) * N + cc) = __floats2half2_rn(v2, v3);
            }
        }
    }
}

// ================= misc kernels =================
// merged weight conversion (float4-vectorized, 5 segments) -> fp16 pairs
#define NWQKV (LAYERS * 3 * H_ * H_)
#define NWO   (LAYERS * H_ * H_)
#define NW1   (LAYERS * 4 * H_ * H_)
#define NW2   (LAYERS * 4 * H_ * H_)
#define NWM   ((LAYERS - 1) * H_ * 3 * H_)
#define NCONV ((NWQKV + NWO + NW1 + NW2 + NWM) / 4)

__global__ __launch_bounds__(256) void conv_all_kernel(
    const float* __restrict__ Wqkv, const float* __restrict__ Wo,
    const float* __restrict__ W1,   const float* __restrict__ W2,
    const float* __restrict__ Wm)
{
    int i4 = blockIdx.x * 256 + threadIdx.x;
    if (i4 >= NCONV) return;
    int i = i4 * 4;
    const float* src; __half *hi, *lo; int off;
    if (i < NWQKV) { src = Wqkv; hi = g_wqkvh; lo = g_wqkvl; off = i; }
    else if (i < NWQKV + NWO) { src = Wo; hi = g_woh; lo = g_wol; off = i - NWQKV; }
    else if (i < NWQKV + NWO + NW1) { src = W1; hi = g_w1h; lo = g_w1l; off = i - NWQKV - NWO; }
    else if (i < NWQKV + NWO + NW1 + NW2) { src = W2; hi = g_w2h; lo = g_w2l; off = i - NWQKV - NWO - NW1; }
    else { src = Wm; hi = g_wmh; lo = g_wml; off = i - NWQKV - NWO - NW1 - NW2; }
    float4 v = *(const float4*)(src + off);
    __half h0, l0, h1, l1, h2, l2, h3, l3;
    split_fp16(v.x, h0, l0); split_fp16(v.y, h1, l1);
    split_fp16(v.z, h2, l2); split_fp16(v.w, h3, l3);
    __half2 p0; p0.x = h0; p0.y = h1;
    __half2 p1; p1.x = h2; p1.y = h3;
    __half2 q0; q0.x = l0; q0.y = l1;
    __half2 q1; q1.x = l2; q1.y = l3;
    *(__half2*)(hi + off)     = p0;
    *(__half2*)(hi + off + 2) = p1;
    *(__half2*)(lo + off)     = q0;
    *(__half2*)(lo + off + 2) = q1;
}

__global__ __launch_bounds__(256) void embed_kernel(
    const float* __restrict__ x, const float* __restrict__ Wfc,
    const float* __restrict__ bfc, const float* __restrict__ cls,
    const float* __restrict__ pos)
{
    int row = blockIdx.x;
    int l  = row % L_;
    int bc = row / L_;
    int c  = bc % C_;
    int b  = bc / C_;
    int t  = threadIdx.x;

    __shared__ float xs[IN_];
    float val;
    if (l < T_) {
        if (t < IN_) xs[t] = x[(((size_t)b * T_ + l) * C_ + c) * IN_ + t];
        __syncthreads();
        float s = bfc[t];
        #pragma unroll
        for (int i = 0; i < IN_; i++) s += xs[i] * Wfc[t * IN_ + i];
        val = s;
    } else {
        val = cls[((l - T_) * C_ + c) * H_ + t];
    }
    val += pos[((size_t)l * C_ + c) * H_ + t];
    size_t o = (size_t)row * H_ + t;
    g_h[o]  = val;
    g_hh[o] = __float2half_rn(val);
}

__global__ __launch_bounds__(256) void graph_kernel(
    const float* __restrict__ emb1, const float* __restrict__ emb2,
    const float* __restrict__ Wl1, const float* __restrict__ bl1,
    const float* __restrict__ Wl2, const float* __restrict__ bl2)
{
    int t = threadIdx.x;
    for (int i = 0; i < C_; i++) {
        float s1 = bl1[t], s2 = bl2[t];
        for (int k = 0; k < H_; k++) {
            s1 += emb1[i * H_ + k] * Wl1[t * H_ + k];
            s2 += emb2[i * H_ + k] * Wl2[t * H_ + k];
        }
        g_m1[i * H_ + t] = tanhf(s1);
        g_m2[i * H_ + t] = tanhf(s2);
    }
    __syncthreads();

    __shared__ float adj[C_][C_];
    __shared__ float rsum[C_];
    int v = t >> 4, w = t & 15;
    float s = 0.f;
    for (int j = 0; j < H_; j++)
        s += g_m1[v * H_ + j] * g_m2[w * H_ + j]
           - g_m2[v * H_ + j] * g_m1[w * H_ + j];
    float gv = fmaxf(tanhf(s), 0.f);
    if (v == w) gv += 1.0f;
    adj[v][w] = gv;
    __syncthreads();
    if (t < C_) {
        float r = 0.f;
        for (int k = 0; k < C_; k++) r += adj[t][k];
        rsum[t] = r;
    }
    __syncthreads();
    g_adj[t] = adj[v][w] / rsum[v];
}

// ================= attention (online softmax, fp16 qkv, fp16 out) ==========
__global__ __launch_bounds__(128) void attn_kernel(const __half* __restrict__ qkv)
{
    int bh = blockIdx.x;
    int b = bh >> 3;
    int h = bh & 7;
    __shared__ float4 Ks[L_][8];
    __shared__ float4 Vs[L_][8];
    const __half* base = qkv + (size_t)b * L_ * (3 * H_) + h * DH_;
    for (int idx = threadIdx.x; idx < L_ * 8; idx += 128) {
        int l = idx >> 3, k4 = idx & 7;
        const __half2* kp = (const __half2*)(base + (size_t)l * (3 * H_) + H_     + k4 * 4);
        const __half2* vp = (const __half2*)(base + (size_t)l * (3 * H_) + 2 * H_ + k4 * 4);
        float2 k0 = __half22float2(kp[0]), k1 = __half22float2(kp[1]);
        float2 vv0 = __half22float2(vp[0]), vv1 = __half22float2(vp[1]);
        Ks[l][k4] = make_float4(k0.x, k0.y, k1.x, k1.y);
        Vs[l][k4] = make_float4(vv0.x, vv0.y, vv1.x, vv1.y);
    }
    __syncthreads();

    int i = threadIdx.x;
    if (i < L_) {
        float4 q[8];
        #pragma unroll
        for (int k4 = 0; k4 < 8; k4++) {
            const __half2* qp = (const __half2*)(base + (size_t)i * (3 * H_) + k4 * 4);
            float2 q0 = __half22float2(qp[0]), q1 = __half22float2(qp[1]);
            q[k4] = make_float4(q0.x, q0.y, q1.x, q1.y);
        }

        float m = -1e30f, lsum = 0.f;
        float4 acc[8];
        #pragma unroll
        for (int k4 = 0; k4 < 8; k4++) acc[k4] = make_float4(0.f, 0.f, 0.f, 0.f);

        int jmax = (i >= T_) ? L_ : (i + 1);
        for (int j = 0; j < jmax; j++) {
            float a0 = 0.f, a1 = 0.f, a2 = 0.f, a3 = 0.f;
            #pragma unroll
            for (int k4 = 0; k4 < 8; k4++) {
                float4 kv = Ks[j][k4];
                a0 += q[k4].x * kv.x;
                a1 += q[k4].y * kv.y;
                a2 += q[k4].z * kv.z;
                a3 += q[k4].w * kv.w;
            }
            float s = ((a0 + a1) + (a2 + a3)) * 0.17677669529663687f;
            if (s <= m) {
                float p = __expf(s - m);
                lsum += p;
                #pragma unroll
                for (int k4 = 0; k4 < 8; k4++) {
                    float4 vv = Vs[j][k4];
                    acc[k4].x += p * vv.x;
                    acc[k4].y += p * vv.y;
                    acc[k4].z += p * vv.z;
                    acc[k4].w += p * vv.w;
                }
            } else {
                float sc = __expf(m - s);
                lsum = lsum * sc + 1.f;
                #pragma unroll
                for (int k4 = 0; k4 < 8; k4++) {
                    float4 vv = Vs[j][k4];
                    acc[k4].x = acc[k4].x * sc + vv.x;
                    acc[k4].y = acc[k4].y * sc + vv.y;
                    acc[k4].z = acc[k4].z * sc + vv.z;
                    acc[k4].w = acc[k4].w * sc + vv.w;
                }
                m = s;
            }
        }
        float inv = 1.f / lsum;
        size_t o = ((size_t)b * L_ + i) * H_ + h * DH_;
        #pragma unroll
        for (int k4 = 0; k4 < 8; k4++) {
            *(__half2*)(g_a + o + k4 * 4)     = __floats2half2_rn(acc[k4].x * inv, acc[k4].y * inv);
            *(__half2*)(g_a + o + k4 * 4 + 2) = __floats2half2_rn(acc[k4].z * inv, acc[k4].w * inv);
        }
    }
}

// fused residual-add + LayerNorm; writes fp32 h and fp16 single
__global__ __launch_bounds__(256) void add_ln_kernel(
    const float* __restrict__ xin,
    const float* __restrict__ g, const float* __restrict__ bt)
{
    int row = blockIdx.x, t = threadIdx.x;
    size_t base = (size_t)row * H_;
    float v = g_h[base + t] + xin[base + t];

    __shared__ float ws[8];
    float s = v;
    #pragma unroll
    for (int o = 16; o > 0; o >>= 1) s += __shfl_xor_sync(0xffffffffu, s, o);
    if ((t & 31) == 0) ws[t >> 5] = s;
    __syncthreads();
    float tot = 0.f;
    #pragma unroll
    for (int i = 0; i < 8; i++) tot += ws[i];
    float mean = tot * (1.0f / H_);
    float d = v - mean;
    __syncthreads();

    float q = d * d;
    #pragma unroll
    for (int o = 16; o > 0; o >>= 1) q += __shfl_xor_sync(0xffffffffu, q, o);
    if ((t & 31) == 0) ws[t >> 5] = q;
    __syncthreads();
    float qt = 0.f;
    #pragma unroll
    for (int i = 0; i < 8; i++) qt += ws[i];
    float var = qt * (1.0f / H_);

    float out = d * rsqrtf(var + EPS_) * g[t] + bt[t];
    g_h[base + t]  = out;
    g_hh[base + t] = __float2half_rn(out);
}

// ---------------- fused mixprop (gather + 2 prop depths + fp16 out) --------
__global__ __launch_bounds__(256) void mp_fused_kernel()
{
    __shared__ float s0[C_ * H_];
    __shared__ float s1[C_ * H_];
    __shared__ float adjs[C_ * C_];

    int n = blockIdx.x >> 2;
    int l = blockIdx.x & 3;
    int t = threadIdx.x;
    adjs[t] = g_adj[t];

    #pragma unroll
    for (int w = 0; w < C_; w++) {
        float v = g_h[(((size_t)(n * C_ + w)) * L_ + T_ + l) * H_ + t];
        s0[w * H_ + t] = v;
        size_t r = (size_t)((n * C_ + w) * NCLS + l) * (3 * H_);
        g_ho[r + t] = __float2half_rn(v);
    }
    __syncthreads();

    #pragma unroll
    for (int v = 0; v < C_; v++) {
        float s = 0.f;
        #pragma unroll
        for (int w = 0; w < C_; w++)
            s += adjs[v * C_ + w] * s0[w * H_ + t];
        s1[v * H_ + t] = s;
        size_t r = (size_t)((n * C_ + v) * NCLS + l) * (3 * H_) + H_;
        g_ho[r + t] = __float2half_rn(s);
    }
    __syncthreads();

    #pragma unroll
    for (int v = 0; v < C_; v++) {
        float s = 0.f;
        #pragma unroll
        for (int w = 0; w < C_; w++)
            s += adjs[v * C_ + w] * s1[w * H_ + t];
        size_t r = (size_t)((n * C_ + v) * NCLS + l) * (3 * H_) + 2 * H_;
        g_ho[r + t] = __float2half_rn(s);
    }
}

__global__ __launch_bounds__(256) void mp_scatter_kernel()
{
    int idx = blockIdx.x * 256 + threadIdx.x;
    int o  = idx & 255;
    int r  = idx >> 8;
    int l  = r & 3;
    int nw = r >> 2;
    float v = g_mpo[(size_t)r * H_ + o];
    size_t dst = ((size_t)nw * L_ + T_ + l) * H_ + o;
    g_h[dst]  = v;
    g_hh[dst] = __float2half_rn(v);
}

// ---------------- head ----------------
__global__ __launch_bounds__(256) void tanh_gather_kernel()
{
    int idx = blockIdx.x * 256 + threadIdx.x;
    int hd = idx & 255;
    int r  = idx >> 8;
    int n  = r & 3;
    int c  = (r >> 2) & 15;
    int b  = r >> 6;
    g_z[idx] = tanhf(g_h[(((size_t)(b * C_ + c)) * L_ + T_ + n) * H_ + hd]);
}

__global__ __launch_bounds__(512) void head_gemm_kernel(
    const float* __restrict__ Wd1, const float* __restrict__ bd1)
{
    extern __shared__ float zs[];
    int b = blockIdx.x;
    int tid = threadIdx.x;
    for (int i = tid; i < C_ * NCLS * H_; i += 512)
        zs[i] = g_z[(size_t)b * (C_ * NCLS * H_) + i];
    __syncthreads();
    int wid = tid >> 5, lane = tid & 31;
    for (int o = wid; o < H_; o += 16) {
        const float* w = Wd1 + (size_t)o * (C_ * NCLS * H_);
        float s = 0.f;
        for (int k = lane; k < C_ * NCLS * H_; k += 32)
            s += zs[k] * w[k];
        #pragma unroll
        for (int off = 16; off > 0; off >>= 1)
            s += __shfl_xor_sync(0xffffffffu, s, off);
        if (lane == 0) g_d1[b * H_ + o] = s + bd1[o];
    }
}

__global__ __launch_bounds__(256) void head_kernel(
    const float* __restrict__ Wd2, const float* __restrict__ bd2,
    float* __restrict__ out)
{
    int b = blockIdx.x, t = threadIdx.x;
    float x = g_d1[b * H_ + t];
    float gl = 0.5f * x * (1.0f + erff(x * 0.70710678118654752f));
    float v = gl * Wd2[t];
    #pragma unroll
    for (int o = 16; o > 0; o >>= 1) v += __shfl_xor_sync(0xffffffffu, v, o);
    __shared__ float ws[8];
    if ((t & 31) == 0) ws[t >> 5] = v;
    __syncthreads();
    if (t == 0) {
        float s = 0.f;
        #pragma unroll
        for (int i = 0; i < 8; i++) s += ws[i];
        out[b] = s + bd2[0];
    }
}

// ---------------- host ----------------
static float* dev_ptr(const void* symbol)
{
    void* p = nullptr;
    cudaGetSymbolAddress(&p, symbol);
    return (float*)p;
}
static __half* dev_ptr_h(const void* symbol)
{
    void* p = nullptr;
    cudaGetSymbolAddress(&p, symbol);
    return (__half*)p;
}

extern "C" void kernel_launch(void* const* d_in, const int* in_sizes, int n_in,
                              void* d_out, int out_size)
{
    const float* x        = (const float*)d_in[0];
    const float* Wfc      = (const float*)d_in[3];
    const float* bfc      = (const float*)d_in[4];
    const float* cls_tok  = (const float*)d_in[5];
    const float* pos_emb  = (const float*)d_in[6];
    const float* emb1     = (const float*)d_in[7];
    const float* emb2     = (const float*)d_in[8];
    const float* Wl1      = (const float*)d_in[9];
    const float* bl1      = (const float*)d_in[10];
    const float* Wl2      = (const float*)d_in[11];
    const float* bl2      = (const float*)d_in[12];
    const float* Wqkv     = (const float*)d_in[13];
    const float* bqkv     = (const float*)d_in[14];
    const float* Wo       = (const float*)d_in[15];
    const float* bo       = (const float*)d_in[16];
    const float* W1       = (const float*)d_in[17];
    const float* b1       = (const float*)d_in[18];
    const float* W2       = (const float*)d_in[19];
    const float* b2       = (const float*)d_in[20];
    const float* ln1g     = (const float*)d_in[21];
    const float* ln1b     = (const float*)d_in[22];
    const float* ln2g     = (const float*)d_in[23];
    const float* ln2b     = (const float*)d_in[24];
    const float* Wmlp     = (const float*)d_in[25];
    const float* bmlp     = (const float*)d_in[26];
    const float* Wd1      = (const float*)d_in[27];
    const float* bd1      = (const float*)d_in[28];
    const float* Wd2      = (const float*)d_in[29];
    const float* bd2      = (const float*)d_in[30];
    float* out = (float*)d_out;

    static bool inited = false;
    static float *p_t1, *p_mpo;
    static __half *p_qkv, *p_hh, *p_a, *p_f1, *p_ho;
    static __half *p_wqkvh, *p_wqkvl, *p_woh, *p_wol, *p_w1h, *p_w1l,
                  *p_w2h, *p_w2l, *p_wmh, *p_wml;
    if (!inited) {
        cudaFuncSetAttribute(gemm_h2_kernel,
            cudaFuncAttributeMaxDynamicSharedMemorySize, SMEM_GEMM_BYTES);
        cudaFuncSetAttribute(head_gemm_kernel,
            cudaFuncAttributeMaxDynamicSharedMemorySize, C_ * NCLS * H_ * 4);
        p_t1 = dev_ptr(g_t1); p_mpo = dev_ptr(g_mpo);
        p_qkv = dev_ptr_h(g_qkv);
        p_hh = dev_ptr_h(g_hh); p_a = dev_ptr_h(g_a);
        p_f1 = dev_ptr_h(g_f1); p_ho = dev_ptr_h(g_ho);
        p_wqkvh = dev_ptr_h(g_wqkvh); p_wqkvl = dev_ptr_h(g_wqkvl);
        p_woh = dev_ptr_h(g_woh); p_wol = dev_ptr_h(g_wol);
        p_w1h = dev_ptr_h(g_w1h); p_w1l = dev_ptr_h(g_w1l);
        p_w2h = dev_ptr_h(g_w2h); p_w2l = dev_ptr_h(g_w2l);
        p_wmh = dev_ptr_h(g_wmh); p_wml = dev_ptr_h(g_wml);
        inited = true;
    }

    // launch 0: merged weight conversion
    conv_all_kernel<<<(NCONV + 255) / 256, 256>>>(Wqkv, Wo, W1, W2, Wmlp);
    // launches 1-2
    graph_kernel<<<1, 256>>>(emb1, emb2, Wl1, bl1, Wl2, bl2);
    embed_kernel<<<ROWS, 256>>>(x, Wfc, bfc, cls_tok, pos_emb);

    const int MP_THREADS = BS * C_ * NCLS * H_;   // 1,048,576

    for (int l = 0; l < LAYERS; l++) {
        if (l > 0) {
            mp_fused_kernel<<<BS * NCLS, 256>>>();
            gemm_h2_kernel<<<dim3(2, 32), 256, SMEM_GEMM_BYTES>>>(
                p_ho,
                p_wmh + (size_t)(l - 1) * H_ * 3 * H_, p_wml + (size_t)(l - 1) * H_ * 3 * H_,
                bmlp + (size_t)(l - 1) * H_,
                p_mpo, nullptr,
                BS * C_ * NCLS, H_, 3 * H_, 0);
            mp_scatter_kernel<<<MP_THREADS / 256, 256>>>();
        }

        // QKV projection -> fp16 (launch 3 on layer 0)
        gemm_h2_kernel<<<dim3(6, ROWS / 128), 256, SMEM_GEMM_BYTES>>>(
            p_hh,
            p_wqkvh + (size_t)l * 3 * H_ * H_, p_wqkvl + (size_t)l * 3 * H_ * H_,
            bqkv + (size_t)l * 3 * H_,
            (float*)p_qkv, nullptr, ROWS, 3 * H_, H_, 2);

        // launch 4 (layer 0)
        attn_kernel<<<BP * NH_, 128>>>(p_qkv);

        // output projection -> g_t1 (launch 5 on layer 0 -> ncu capture)
        gemm_h2_kernel<<<dim3(2, ROWS / 128), 256, SMEM_GEMM_BYTES>>>(
            p_a,
            p_woh + (size_t)l * H_ * H_, p_wol + (size_t)l * H_ * H_,
            bo + (size_t)l * H_,
            p_t1, nullptr, ROWS, H_, H_, 0);

        add_ln_kernel<<<ROWS, 256>>>(p_t1, ln1g + l * H_, ln1b + l * H_);

        // FFN
        gemm_h2_kernel<<<dim3(8, ROWS / 128), 256, SMEM_GEMM_BYTES>>>(
            p_hh,
            p_w1h + (size_t)l * 4 * H_ * H_, p_w1l + (size_t)l * 4 * H_ * H_,
            b1 + (size_t)l * 4 * H_,
            nullptr, p_f1, ROWS, 4 * H_, H_, 1);

        gemm_h2_kernel<<<dim3(2, ROWS / 128), 256, SMEM_GEMM_BYTES>>>(
            p_f1,
            p_w2h + (size_t)l * 4 * H_ * H_, p_w2l + (size_t)l * 4 * H_ * H_,
            b2 + (size_t)l * H_,
            p_t1, nullptr, ROWS, H_, 4 * H_, 0);

        add_ln_kernel<<<ROWS, 256>>>(p_t1, ln2g + l * H_, ln2b + l * H_);
    }

    tanh_gather_kernel<<<MP_THREADS / 256, 256>>>();
    head_gemm_kernel<<<BS, 512, C_ * NCLS * H_ * 4>>>(Wd1, bd1);
    head_kernel<<<BS, 256>>>(Wd2, bd2, out);
}